// round 5
// baseline (speedup 1.0000x reference)
#include <cuda_runtime.h>
#include <cuda_bf16.h>
#include <cstdint>

// ---------------- problem constants ----------------
#define B_    2
#define S_    1024
#define HID_  2048
#define H_    32
#define HK_   4
#define D_    128
#define G_    (H_ / HK_)              // 8
#define NQKV_ ((H_ + 2 * HK_) * D_)   // 5120
#define BS_   (B_ * S_)               // 2048
#define EPS_  1e-6f
#define SCALE_ 0.08838834764831845f   // 1/sqrt(128)

// ---------------- scratch (static device memory; no allocs allowed) ----------------
__device__ float g_qkv[(size_t)BS_ * NQKV_];        // [2048, 5120]
__device__ float g_q  [(size_t)BS_ * H_  * D_];     // [2048, 32, 128]
__device__ float g_k  [(size_t)BS_ * HK_ * D_];     // [2048, 4, 128]
__device__ float g_ctx[(size_t)BS_ * H_  * D_];     // [2048, 4096]

// ============================================================================
// SGEMM: C[M,N] = A[M,K] @ B[K,N], row-major, all dims % 128 == 0, K % 8 == 0.
// 128x128 block tile, BK=8, 256 threads, 8x8 per-thread microtile, double buffer.
// ============================================================================
__global__ __launch_bounds__(256)
void sgemm_kernel(int M, int N, int K,
                  const float* __restrict__ A,
                  const float* __restrict__ Bm,
                  float* __restrict__ C)
{
    __shared__ float As[2][8][128];   // [buf][k][m]  (A stored transposed)
    __shared__ float Bs[2][8][128];   // [buf][k][n]

    const int tid = threadIdx.x;
    const int bx = blockIdx.x;        // N tile
    const int by = blockIdx.y;        // M tile
    const int tx = tid & 15;
    const int ty = tid >> 4;

    const float* Ab = A  + (size_t)by * 128 * K;
    const float* Bb = Bm + (size_t)bx * 128;

    const int arow = tid >> 1;             // 0..127
    const int acol = (tid & 1) * 4;        // 0 or 4
    const int brow = tid >> 5;             // 0..7
    const int bcol = (tid & 31) * 4;       // 0..124

    // preload tile 0
    float4 av = *(const float4*)(Ab + (size_t)arow * K + acol);
    float4 bv = *(const float4*)(Bb + (size_t)brow * N + bcol);
    As[0][acol + 0][arow] = av.x;
    As[0][acol + 1][arow] = av.y;
    As[0][acol + 2][arow] = av.z;
    As[0][acol + 3][arow] = av.w;
    *(float4*)&Bs[0][brow][bcol] = bv;
    __syncthreads();

    float c[8][8];
    #pragma unroll
    for (int i = 0; i < 8; i++)
        #pragma unroll
        for (int j = 0; j < 8; j++) c[i][j] = 0.f;

    const int ntiles = K >> 3;
    int buf = 0;
    for (int t = 0; t < ntiles; ++t) {
        if (t + 1 < ntiles) {
            int k0 = (t + 1) << 3;
            av = *(const float4*)(Ab + (size_t)arow * K + k0 + acol);
            bv = *(const float4*)(Bb + (size_t)(k0 + brow) * N + bcol);
        }
        #pragma unroll
        for (int kk = 0; kk < 8; ++kk) {
            float4 a0 = *(const float4*)&As[buf][kk][ty * 8];
            float4 a1 = *(const float4*)&As[buf][kk][ty * 8 + 4];
            float4 b0 = *(const float4*)&Bs[buf][kk][tx * 8];
            float4 b1 = *(const float4*)&Bs[buf][kk][tx * 8 + 4];
            float a[8] = {a0.x, a0.y, a0.z, a0.w, a1.x, a1.y, a1.z, a1.w};
            float b[8] = {b0.x, b0.y, b0.z, b0.w, b1.x, b1.y, b1.z, b1.w};
            #pragma unroll
            for (int i = 0; i < 8; i++)
                #pragma unroll
                for (int j = 0; j < 8; j++)
                    c[i][j] += a[i] * b[j];
        }
        if (t + 1 < ntiles) {
            As[buf ^ 1][acol + 0][arow] = av.x;
            As[buf ^ 1][acol + 1][arow] = av.y;
            As[buf ^ 1][acol + 2][arow] = av.z;
            As[buf ^ 1][acol + 3][arow] = av.w;
            *(float4*)&Bs[buf ^ 1][brow][bcol] = bv;
        }
        buf ^= 1;
        __syncthreads();
    }

    float* Cb = C + (size_t)(by * 128 + ty * 8) * N + bx * 128 + tx * 8;
    #pragma unroll
    for (int i = 0; i < 8; i++) {
        *(float4*)(Cb + (size_t)i * N)     = make_float4(c[i][0], c[i][1], c[i][2], c[i][3]);
        *(float4*)(Cb + (size_t)i * N + 4) = make_float4(c[i][4], c[i][5], c[i][6], c[i][7]);
    }
}

// ============================================================================
// Fused per-head RMSNorm + RoPE for q and k heads.
// grid: (BS_, H_ + HK_), block: 128 threads (one per d).
// ============================================================================
__global__ __launch_bounds__(128)
void normrope_kernel(const float* __restrict__ cosb,
                     const float* __restrict__ sinb,
                     const float* __restrict__ qw,
                     const float* __restrict__ kw)
{
    const int t  = blockIdx.x;           // token 0..2047
    const int hh = blockIdx.y;           // 0..35
    const int d  = threadIdx.x;          // 0..127
    const int s  = t & (S_ - 1);         // position within sequence

    const float* src;
    const float* w;
    float* dst;
    if (hh < H_) {
        src = g_qkv + (size_t)t * NQKV_ + hh * D_;
        w   = qw;
        dst = g_q + ((size_t)t * H_ + hh) * D_;
    } else {
        int kh = hh - H_;
        src = g_qkv + (size_t)t * NQKV_ + (H_ + kh) * D_;
        w   = kw;
        dst = g_k + ((size_t)t * HK_ + kh) * D_;
    }

    float x = src[d];
    float v = x * x;
    #pragma unroll
    for (int o = 16; o > 0; o >>= 1)
        v += __shfl_xor_sync(0xffffffffu, v, o);

    __shared__ float red[4];
    __shared__ float xn_s[D_];
    int warp = d >> 5, lane = d & 31;
    if (lane == 0) red[warp] = v;
    __syncthreads();
    float total = red[0] + red[1] + red[2] + red[3];
    float xn = w[d] * x * rsqrtf(total * (1.0f / D_) + EPS_);
    xn_s[d] = xn;
    __syncthreads();
    float other = (d < 64) ? xn_s[d + 64] : xn_s[d - 64];
    float rot   = (d < 64) ? -other : other;
    dst[d] = xn * cosb[s * D_ + d] + rot * sinb[s * D_ + d];
}

// ============================================================================
// Flash attention (causal, GQA). One block = 64 query rows of one (b, h).
// 256 threads. O accumulator (64x128) in registers: each thread owns 4x8.
// ============================================================================
#define ABM 64
#define ABN 64

struct AttnSmem {
    float Qs[128][ABM];     // [d][q]   (k-major)  32 KB
    float Ks[128][ABN];     // [d][kv]             32 KB
    float Vs[ABN][128];     // [kv][d]             32 KB
    float Ps[ABM][65];      // scores/probs, padded 16.25 KB
    float m_s[ABM];
    float l_s[ABM];
    float al_s[ABM];
};

extern __shared__ char attn_smem_raw[];

__global__ __launch_bounds__(256)
void attn_kernel()
{
    AttnSmem& sm = *reinterpret_cast<AttnSmem*>(attn_smem_raw);
    const int tid = threadIdx.x;
    const int qt = blockIdx.x;     // 0..15
    const int h  = blockIdx.y;     // 0..31
    const int b  = blockIdx.z;     // 0..1
    const int kh = h / G_;
    const int tx = tid & 15;
    const int ty = tid >> 4;
    const int t0 = b * S_ + qt * ABM;

    // ---- load Q tile (transposed) ----
    #pragma unroll
    for (int it = 0; it < 8; ++it) {
        int lin = it * 256 + tid;        // 0..2047 float4 indices
        int r   = lin >> 5;
        int d4  = (lin & 31) << 2;
        float4 v = *(const float4*)&g_q[((size_t)(t0 + r) * H_ + h) * D_ + d4];
        sm.Qs[d4 + 0][r] = v.x;
        sm.Qs[d4 + 1][r] = v.y;
        sm.Qs[d4 + 2][r] = v.z;
        sm.Qs[d4 + 3][r] = v.w;
    }
    if (tid < ABM) { sm.m_s[tid] = -1e30f; sm.l_s[tid] = 0.f; }

    float o[4][8];
    #pragma unroll
    for (int i = 0; i < 4; i++)
        #pragma unroll
        for (int j = 0; j < 8; j++) o[i][j] = 0.f;

    for (int j = 0; j <= qt; ++j) {
        __syncthreads();   // Q visible (j==0); previous PV done before K/V overwrite

        // ---- load K (transposed) and V (row-major) tiles ----
        const int kt0 = b * S_ + j * ABN;
        #pragma unroll
        for (int it = 0; it < 8; ++it) {
            int lin = it * 256 + tid;
            int r   = lin >> 5;
            int d4  = (lin & 31) << 2;
            float4 kv = *(const float4*)&g_k[((size_t)(kt0 + r) * HK_ + kh) * D_ + d4];
            sm.Ks[d4 + 0][r] = kv.x;
            sm.Ks[d4 + 1][r] = kv.y;
            sm.Ks[d4 + 2][r] = kv.z;
            sm.Ks[d4 + 3][r] = kv.w;
            float4 vv = *(const float4*)&g_qkv[(size_t)(kt0 + r) * NQKV_ + (H_ + HK_) * D_ + kh * D_ + d4];
            *(float4*)&sm.Vs[r][d4] = vv;
        }
        __syncthreads();

        // ---- S = Q @ K^T (4x4 per thread) ----
        float sc[4][4];
        #pragma unroll
        for (int i = 0; i < 4; i++)
            #pragma unroll
            for (int jj = 0; jj < 4; jj++) sc[i][jj] = 0.f;

        #pragma unroll 8
        for (int k = 0; k < 128; ++k) {
            float4 qa = *(const float4*)&sm.Qs[k][ty * 4];
            float4 kb = *(const float4*)&sm.Ks[k][tx * 4];
            float a[4] = {qa.x, qa.y, qa.z, qa.w};
            float bb[4] = {kb.x, kb.y, kb.z, kb.w};
            #pragma unroll
            for (int i = 0; i < 4; i++)
                #pragma unroll
                for (int jj = 0; jj < 4; jj++)
                    sc[i][jj] += a[i] * bb[jj];
        }

        const bool diag = (j == qt);
        #pragma unroll
        for (int i = 0; i < 4; i++)
            #pragma unroll
            for (int jj = 0; jj < 4; jj++) {
                float sv = sc[i][jj] * SCALE_;
                if (diag && (tx * 4 + jj > ty * 4 + i)) sv = -1e30f;
                sm.Ps[ty * 4 + i][tx * 4 + jj] = sv;
            }
        __syncthreads();

        // ---- online softmax (4 threads per row) ----
        {
            int row = tid >> 2, q4 = tid & 3;
            float vals[16];
            float mloc = -1e30f;
            #pragma unroll
            for (int kk = 0; kk < 16; kk++) {
                vals[kk] = sm.Ps[row][q4 * 16 + kk];
                mloc = fmaxf(mloc, vals[kk]);
            }
            mloc = fmaxf(mloc, __shfl_xor_sync(0xffffffffu, mloc, 1));
            mloc = fmaxf(mloc, __shfl_xor_sync(0xffffffffu, mloc, 2));
            float mold = sm.m_s[row];
            float mnew = fmaxf(mold, mloc);
            float ssum = 0.f;
            #pragma unroll
            for (int kk = 0; kk < 16; kk++) {
                float p = __expf(vals[kk] - mnew);
                sm.Ps[row][q4 * 16 + kk] = p;
                ssum += p;
            }
            ssum += __shfl_xor_sync(0xffffffffu, ssum, 1);
            ssum += __shfl_xor_sync(0xffffffffu, ssum, 2);
            if (q4 == 0) {
                float alpha = __expf(mold - mnew);
                sm.al_s[row] = alpha;
                sm.m_s[row]  = mnew;
                sm.l_s[row]  = sm.l_s[row] * alpha + ssum;
            }
        }
        __syncthreads();

        // ---- O = O*alpha + P @ V (4x8 per thread) ----
        float alr[4];
        #pragma unroll
        for (int i = 0; i < 4; i++) alr[i] = sm.al_s[ty * 4 + i];
        #pragma unroll
        for (int i = 0; i < 4; i++)
            #pragma unroll
            for (int jj = 0; jj < 8; jj++) o[i][jj] *= alr[i];

        #pragma unroll 4
        for (int k = 0; k < ABN; ++k) {
            float p0 = sm.Ps[ty * 4 + 0][k];
            float p1 = sm.Ps[ty * 4 + 1][k];
            float p2 = sm.Ps[ty * 4 + 2][k];
            float p3 = sm.Ps[ty * 4 + 3][k];
            float4 v0 = *(const float4*)&sm.Vs[k][tx * 8];
            float4 v1 = *(const float4*)&sm.Vs[k][tx * 8 + 4];
            float vv[8] = {v0.x, v0.y, v0.z, v0.w, v1.x, v1.y, v1.z, v1.w};
            #pragma unroll
            for (int jj = 0; jj < 8; jj++) {
                o[0][jj] += p0 * vv[jj];
                o[1][jj] += p1 * vv[jj];
                o[2][jj] += p2 * vv[jj];
                o[3][jj] += p3 * vv[jj];
            }
        }
    }

    // ---- epilogue: divide by l, write ctx ----
    float linv[4];
    #pragma unroll
    for (int i = 0; i < 4; i++) linv[i] = 1.f / sm.l_s[ty * 4 + i];
    #pragma unroll
    for (int i = 0; i < 4; i++) {
        size_t base = ((size_t)(t0 + ty * 4 + i) * H_ + h) * D_ + tx * 8;
        *(float4*)&g_ctx[base]     = make_float4(o[i][0] * linv[i], o[i][1] * linv[i],
                                                 o[i][2] * linv[i], o[i][3] * linv[i]);
        *(float4*)&g_ctx[base + 4] = make_float4(o[i][4] * linv[i], o[i][5] * linv[i],
                                                 o[i][6] * linv[i], o[i][7] * linv[i]);
    }
}

// ============================================================================
// launch
// ============================================================================
extern "C" void kernel_launch(void* const* d_in, const int* in_sizes, int n_in,
                              void* d_out, int out_size)
{
    (void)in_sizes; (void)n_in; (void)out_size;
    const float* hs   = (const float*)d_in[0];
    const float* cosb = (const float*)d_in[1];
    const float* sinb = (const float*)d_in[2];
    const float* wqkv = (const float*)d_in[3];
    const float* qw   = (const float*)d_in[4];
    const float* kw   = (const float*)d_in[5];
    const float* wo   = (const float*)d_in[6];
    float* out = (float*)d_out;

    float *qkv_p, *ctx_p;
    cudaGetSymbolAddress((void**)&qkv_p, g_qkv);
    cudaGetSymbolAddress((void**)&ctx_p, g_ctx);

    // 1) qkv = hidden @ w_qkv    [2048,2048] x [2048,5120]
    sgemm_kernel<<<dim3(NQKV_ / 128, BS_ / 128), 256>>>(BS_, NQKV_, HID_, hs, wqkv, qkv_p);

    // 2) per-head RMSNorm + RoPE into g_q / g_k
    normrope_kernel<<<dim3(BS_, H_ + HK_), 128>>>(cosb, sinb, qw, kw);

    // 3) GQA causal flash attention -> g_ctx
    size_t smem = sizeof(AttnSmem);
    cudaFuncSetAttribute(attn_kernel, cudaFuncAttributeMaxDynamicSharedMemorySize, (int)smem);
    attn_kernel<<<dim3(S_ / ABM, H_, B_), 256, smem>>>();

    // 4) out = ctx @ w_o         [2048,4096] x [4096,2048]
    sgemm_kernel<<<dim3(HID_ / 128, BS_ / 128), 256>>>(BS_, HID_, H_ * D_, ctx_p, wo, out);
}

// round 11
// speedup vs baseline: 2.1319x; 2.1319x over previous
#include <cuda_runtime.h>
#include <cuda_bf16.h>
#include <cstdint>

// ---------------- problem constants ----------------
#define B_    2
#define S_    1024
#define HID_  2048
#define H_    32
#define HK_   4
#define D_    128
#define G_    (H_ / HK_)              // 8
#define NQKV_ ((H_ + 2 * HK_) * D_)   // 5120
#define BS_   (B_ * S_)               // 2048
#define EPS_  1e-6f
#define SCALE_ 0.08838834764831845f   // 1/sqrt(128)

// ---------------- scratch (static device memory; no allocs allowed) ----------------
__device__ float g_qkv  [(size_t)BS_ * NQKV_];        // [2048, 5120]
__device__ float g_q    [(size_t)BS_ * H_  * D_];     // [2048, 32, 128]
__device__ float g_k    [(size_t)BS_ * HK_ * D_];     // [2048, 4, 128]
__device__ float g_ctx  [(size_t)BS_ * H_  * D_];     // [2048, 4096]
__device__ float g_wqkvT[(size_t)NQKV_ * HID_];       // [5120, 2048]  (w_qkv^T)
__device__ float g_woT  [(size_t)HID_ * (H_ * D_)];   // [2048, 4096]  (w_o^T)

extern __shared__ char dyn_smem[];

// ---------------- helpers ----------------
__device__ __forceinline__ uint32_t f2tf(float x) {   // round-to-nearest tf32
    uint32_t r;
    asm("cvt.rna.tf32.f32 %0, %1;" : "=r"(r) : "f"(x));
    return r;
}
__device__ __forceinline__ float tf2f(float x) { return __uint_as_float(f2tf(x)); }

// mma.sync m16n8k8 tf32: D(f32) = A(tf32,row) * B(tf32,col) + D
#define MMA_TF32(c, a, b)                                                      \
    asm volatile(                                                              \
        "mma.sync.aligned.m16n8k8.row.col.f32.tf32.tf32.f32 "                  \
        "{%0,%1,%2,%3}, {%4,%5,%6,%7}, {%8,%9}, {%0,%1,%2,%3};"                \
        : "+f"((c)[0]), "+f"((c)[1]), "+f"((c)[2]), "+f"((c)[3])               \
        : "r"((a)[0]), "r"((a)[1]), "r"((a)[2]), "r"((a)[3]),                  \
          "r"((b)[0]), "r"((b)[1]))

// Fragment layouts (lane = threadIdx.x & 31):
//  A m16k8: a0=(r,c) a1=(r+8,c) a2=(r,c+4) a3=(r+8,c+4), r=lane>>2, c=lane&3
//  B k8n8 : b0=(k,n) b1=(k+4,n),                         k=lane&3, n=lane>>2
//  C m16n8: c0=(r,2t) c1=(r,2t+1) c2=(r+8,2t) c3=(r+8,2t+1), t=lane&3

// ============================================================================
// tf32 tensor-core GEMM: C[M,N] = A[M,K] @ Bt[N,K]^T   (both row-major inputs)
// 128x128 CTA tile, BK=32, 256 threads (8 warps in 2Mx4N), reg-prefetch DB.
// Smem rows padded to 36 floats -> all frag lds.32 conflict-free.
// ============================================================================
#define SROW 36
#define GEMM_SMEM (4 * 128 * SROW * 4)   // A0,A1,B0,B1 = 73728 B

__global__ __launch_bounds__(256, 1)
void mma_gemm_kernel(int M, int N, int K,
                     const float* __restrict__ A,
                     const float* __restrict__ Bt,
                     float* __restrict__ C)
{
    float* sm = (float*)dyn_smem;
    float* Asm[2] = { sm,               sm + 128 * SROW };
    float* Bsm[2] = { sm + 2*128*SROW,  sm + 3*128*SROW };

    const int tid  = threadIdx.x;
    const int lane = tid & 31;
    const int wid  = tid >> 5;
    const int wm   = (wid & 1) * 64;    // warp M offset
    const int wn   = (wid >> 1) * 32;   // warp N offset
    const int m0 = blockIdx.y * 128;
    const int n0 = blockIdx.x * 128;

    const int srow = tid >> 3;          // 0..31? no: 256 threads -> lin below
    (void)srow;

    float acc[4][4][4];
    #pragma unroll
    for (int i = 0; i < 4; i++)
        #pragma unroll
        for (int j = 0; j < 4; j++)
            #pragma unroll
            for (int r = 0; r < 4; r++) acc[i][j][r] = 0.f;

    const int ntc = K >> 5;

    // ---- preload chunk 0 ----
    #pragma unroll
    for (int i = 0; i < 4; ++i) {
        int lin = i * 256 + tid;          // 0..1023
        int row = lin >> 3;               // 0..127
        int c4  = (lin & 7) * 4;          // 0..28
        float4 va = *(const float4*)(A  + (size_t)(m0 + row) * K + c4);
        float4 vb = *(const float4*)(Bt + (size_t)(n0 + row) * K + c4);
        float* pa = Asm[0] + row * SROW + c4;
        float* pb = Bsm[0] + row * SROW + c4;
        pa[0] = tf2f(va.x); pa[1] = tf2f(va.y); pa[2] = tf2f(va.z); pa[3] = tf2f(va.w);
        pb[0] = tf2f(vb.x); pb[1] = tf2f(vb.y); pb[2] = tf2f(vb.z); pb[3] = tf2f(vb.w);
    }
    __syncthreads();

    for (int t = 0; t < ntc; ++t) {
        const int buf = t & 1;
        float4 pfa[4], pfb[4];
        if (t + 1 < ntc) {
            const int k0 = (t + 1) << 5;
            #pragma unroll
            for (int i = 0; i < 4; ++i) {
                int lin = i * 256 + tid;
                int row = lin >> 3;
                int c4  = (lin & 7) * 4;
                pfa[i] = *(const float4*)(A  + (size_t)(m0 + row) * K + k0 + c4);
                pfb[i] = *(const float4*)(Bt + (size_t)(n0 + row) * K + k0 + c4);
            }
        }

        // ---- compute chunk: 4 k-steps of 8 ----
        const float* Ab = Asm[buf];
        const float* Bb = Bsm[buf];
        #pragma unroll
        for (int ks = 0; ks < 4; ++ks) {
            uint32_t afr[4][4];
            #pragma unroll
            for (int mt = 0; mt < 4; ++mt) {
                const float* ap = Ab + (wm + mt * 16 + (lane >> 2)) * SROW + ks * 8 + (lane & 3);
                afr[mt][0] = __float_as_uint(ap[0]);
                afr[mt][1] = __float_as_uint(ap[8 * SROW]);
                afr[mt][2] = __float_as_uint(ap[4]);
                afr[mt][3] = __float_as_uint(ap[8 * SROW + 4]);
            }
            uint32_t bfr[4][2];
            #pragma unroll
            for (int nt = 0; nt < 4; ++nt) {
                const float* bp = Bb + (wn + nt * 8 + (lane >> 2)) * SROW + ks * 8 + (lane & 3);
                bfr[nt][0] = __float_as_uint(bp[0]);
                bfr[nt][1] = __float_as_uint(bp[4]);
            }
            #pragma unroll
            for (int mt = 0; mt < 4; ++mt)
                #pragma unroll
                for (int nt = 0; nt < 4; ++nt)
                    MMA_TF32(acc[mt][nt], afr[mt], bfr[nt]);
        }

        if (t + 1 < ntc) {
            #pragma unroll
            for (int i = 0; i < 4; ++i) {
                int lin = i * 256 + tid;
                int row = lin >> 3;
                int c4  = (lin & 7) * 4;
                float* pa = Asm[buf ^ 1] + row * SROW + c4;
                float* pb = Bsm[buf ^ 1] + row * SROW + c4;
                pa[0] = tf2f(pfa[i].x); pa[1] = tf2f(pfa[i].y); pa[2] = tf2f(pfa[i].z); pa[3] = tf2f(pfa[i].w);
                pb[0] = tf2f(pfb[i].x); pb[1] = tf2f(pfb[i].y); pb[2] = tf2f(pfb[i].z); pb[3] = tf2f(pfb[i].w);
            }
        }
        __syncthreads();
    }

    // ---- epilogue ----
    #pragma unroll
    for (int mt = 0; mt < 4; ++mt) {
        #pragma unroll
        for (int nt = 0; nt < 4; ++nt) {
            int r0 = m0 + wm + mt * 16 + (lane >> 2);
            int cc = n0 + wn + nt * 8 + (lane & 3) * 2;
            *(float2*)(C + (size_t)r0 * N + cc)       = make_float2(acc[mt][nt][0], acc[mt][nt][1]);
            *(float2*)(C + (size_t)(r0 + 8) * N + cc) = make_float2(acc[mt][nt][2], acc[mt][nt][3]);
        }
    }
}

// ============================================================================
// Tiled transpose: out[C, R] = in[R, C]^T
// ============================================================================
__global__ __launch_bounds__(256)
void transpose_kernel(const float* __restrict__ in, float* __restrict__ out, int R, int C)
{
    __shared__ float tile[32][33];
    const int c0 = blockIdx.x * 32;
    const int r0 = blockIdx.y * 32;
    const int tx = threadIdx.x, ty = threadIdx.y;
    #pragma unroll
    for (int i = 0; i < 4; ++i)
        tile[ty + i * 8][tx] = in[(size_t)(r0 + ty + i * 8) * C + c0 + tx];
    __syncthreads();
    #pragma unroll
    for (int i = 0; i < 4; ++i)
        out[(size_t)(c0 + ty + i * 8) * R + r0 + tx] = tile[tx][ty + i * 8];
}

// ============================================================================
// Fused per-head RMSNorm + RoPE for q and k heads.
// ============================================================================
__global__ __launch_bounds__(128)
void normrope_kernel(const float* __restrict__ cosb,
                     const float* __restrict__ sinb,
                     const float* __restrict__ qw,
                     const float* __restrict__ kw)
{
    const int t  = blockIdx.x;
    const int hh = blockIdx.y;
    const int d  = threadIdx.x;
    const int s  = t & (S_ - 1);

    const float* src;
    const float* w;
    float* dst;
    if (hh < H_) {
        src = g_qkv + (size_t)t * NQKV_ + hh * D_;
        w   = qw;
        dst = g_q + ((size_t)t * H_ + hh) * D_;
    } else {
        int kh = hh - H_;
        src = g_qkv + (size_t)t * NQKV_ + (H_ + kh) * D_;
        w   = kw;
        dst = g_k + ((size_t)t * HK_ + kh) * D_;
    }

    float x = src[d];
    float v = x * x;
    #pragma unroll
    for (int o = 16; o > 0; o >>= 1)
        v += __shfl_xor_sync(0xffffffffu, v, o);

    __shared__ float red[4];
    __shared__ float xn_s[D_];
    int warp = d >> 5, lane = d & 31;
    if (lane == 0) red[warp] = v;
    __syncthreads();
    float total = red[0] + red[1] + red[2] + red[3];
    float xn = w[d] * x * rsqrtf(total * (1.0f / D_) + EPS_);
    xn_s[d] = xn;
    __syncthreads();
    float other = (d < 64) ? xn_s[d + 64] : xn_s[d - 64];
    float rot   = (d < 64) ? -other : other;
    dst[d] = xn * cosb[s * D_ + d] + rot * sinb[s * D_ + d];
}

// ============================================================================
// Flash attention (causal, GQA) with tf32 mma.sync matmuls + fp32 softmax.
// One block = 64 q rows of one (b, h). 256 threads = 8 warps.
//   S phase: warp (qw=wid&3, kvw=wid>>2): S tile m16(q) x n32(kv), K=128.
//   PV phase: warp (qw=wid&3, dw=wid>>2): O tile m16(q) x n64(d), K=64.
// Pads: Q/K stride 132 (≡4 mod 32), P stride 68 (≡4), V stride 136 (≡8):
// all fragment lds.32 are bank-conflict-free.
// ============================================================================
#define ABM 64
#define ABN 64
#define QPAD 132
#define KPAD 132
#define VPAD 136
#define PPAD 68

struct AttnSmem {
    float Qs[ABM][QPAD];
    float Ks[ABN][KPAD];
    float Vs[ABN][VPAD];
    float Ps[ABM][PPAD];
    float m_s[ABM];
    float l_s[ABM];
    float al_s[ABM];
};

__global__ __launch_bounds__(256, 1)
void attn_kernel()
{
    AttnSmem& sm = *reinterpret_cast<AttnSmem*>(dyn_smem);
    const int tid  = threadIdx.x;
    const int lane = tid & 31;
    const int wid  = tid >> 5;
    const int qw   = (wid & 3) * 16;    // q-row group (shared by S and PV phases)
    const int kvw  = (wid >> 2) * 32;   // kv-col group (S phase)
    const int dw   = (wid >> 2) * 64;   // d-col group (PV phase)

    const int qt = blockIdx.x;
    const int h  = blockIdx.y;
    const int b  = blockIdx.z;
    const int kh = h / G_;
    const int t0 = b * S_ + qt * ABM;

    // ---- load Q tile (row-major, tf32-rounded) ----
    #pragma unroll
    for (int it = 0; it < 8; ++it) {
        int lin = it * 256 + tid;        // 0..2047
        int r   = lin >> 5;              // 0..63
        int d4  = (lin & 31) << 2;
        float4 v = *(const float4*)&g_q[((size_t)(t0 + r) * H_ + h) * D_ + d4];
        sm.Qs[r][d4 + 0] = tf2f(v.x);
        sm.Qs[r][d4 + 1] = tf2f(v.y);
        sm.Qs[r][d4 + 2] = tf2f(v.z);
        sm.Qs[r][d4 + 3] = tf2f(v.w);
    }
    if (tid < ABM) { sm.m_s[tid] = -1e30f; sm.l_s[tid] = 0.f; }

    float o[8][4];
    #pragma unroll
    for (int i = 0; i < 8; i++)
        #pragma unroll
        for (int j = 0; j < 4; j++) o[i][j] = 0.f;

    for (int j = 0; j <= qt; ++j) {
        __syncthreads();   // Q visible (j==0); prev PV reads done before K/V/P overwrite

        // ---- load K, V tiles (tf32-rounded) ----
        const int kt0 = b * S_ + j * ABN;
        #pragma unroll
        for (int it = 0; it < 8; ++it) {
            int lin = it * 256 + tid;
            int r   = lin >> 5;
            int d4  = (lin & 31) << 2;
            float4 kv = *(const float4*)&g_k[((size_t)(kt0 + r) * HK_ + kh) * D_ + d4];
            sm.Ks[r][d4 + 0] = tf2f(kv.x);
            sm.Ks[r][d4 + 1] = tf2f(kv.y);
            sm.Ks[r][d4 + 2] = tf2f(kv.z);
            sm.Ks[r][d4 + 3] = tf2f(kv.w);
            float4 vv = *(const float4*)&g_qkv[(size_t)(kt0 + r) * NQKV_ + (H_ + HK_) * D_ + kh * D_ + d4];
            sm.Vs[r][d4 + 0] = tf2f(vv.x);
            sm.Vs[r][d4 + 1] = tf2f(vv.y);
            sm.Vs[r][d4 + 2] = tf2f(vv.z);
            sm.Vs[r][d4 + 3] = tf2f(vv.w);
        }
        __syncthreads();

        // ---- S = Q @ K^T via mma (per warp: m16 x n32, K=128) ----
        float s[4][4];
        #pragma unroll
        for (int nt = 0; nt < 4; ++nt)
            #pragma unroll
            for (int r = 0; r < 4; ++r) s[nt][r] = 0.f;

        #pragma unroll
        for (int ks = 0; ks < 16; ++ks) {
            uint32_t afr[4];
            const float* ap = &sm.Qs[qw + (lane >> 2)][ks * 8 + (lane & 3)];
            afr[0] = __float_as_uint(ap[0]);
            afr[1] = __float_as_uint(ap[8 * QPAD]);
            afr[2] = __float_as_uint(ap[4]);
            afr[3] = __float_as_uint(ap[8 * QPAD + 4]);
            #pragma unroll
            for (int nt = 0; nt < 4; ++nt) {
                const float* bp = &sm.Ks[kvw + nt * 8 + (lane >> 2)][ks * 8 + (lane & 3)];
                uint32_t bfr[2] = { __float_as_uint(bp[0]), __float_as_uint(bp[4]) };
                MMA_TF32(s[nt], afr, bfr);
            }
        }

        // ---- write S to Ps with scale + causal mask ----
        const bool diag = (j == qt);
        const int sr = qw + (lane >> 2);
        #pragma unroll
        for (int nt = 0; nt < 4; ++nt) {
            int cc = kvw + nt * 8 + (lane & 3) * 2;
            float v0 = s[nt][0] * SCALE_;
            float v1 = s[nt][1] * SCALE_;
            float v2 = s[nt][2] * SCALE_;
            float v3 = s[nt][3] * SCALE_;
            if (diag) {
                if (cc     > sr)     v0 = -1e30f;
                if (cc + 1 > sr)     v1 = -1e30f;
                if (cc     > sr + 8) v2 = -1e30f;
                if (cc + 1 > sr + 8) v3 = -1e30f;
            }
            sm.Ps[sr][cc]     = v0;
            sm.Ps[sr][cc + 1] = v1;
            sm.Ps[sr + 8][cc]     = v2;
            sm.Ps[sr + 8][cc + 1] = v3;
        }
        __syncthreads();

        // ---- online softmax (4 threads per row), fp32 ----
        {
            int row = tid >> 2, q4 = tid & 3;
            float vals[16];
            float mloc = -1e30f;
            #pragma unroll
            for (int kk = 0; kk < 16; kk++) {
                vals[kk] = sm.Ps[row][q4 * 16 + kk];
                mloc = fmaxf(mloc, vals[kk]);
            }
            mloc = fmaxf(mloc, __shfl_xor_sync(0xffffffffu, mloc, 1));
            mloc = fmaxf(mloc, __shfl_xor_sync(0xffffffffu, mloc, 2));
            float mold = sm.m_s[row];
            float mnew = fmaxf(mold, mloc);
            float ssum = 0.f;
            #pragma unroll
            for (int kk = 0; kk < 16; kk++) {
                float p = __expf(vals[kk] - mnew);
                sm.Ps[row][q4 * 16 + kk] = p;
                ssum += p;
            }
            ssum += __shfl_xor_sync(0xffffffffu, ssum, 1);
            ssum += __shfl_xor_sync(0xffffffffu, ssum, 2);
            if (q4 == 0) {
                float alpha = __expf(mold - mnew);
                sm.al_s[row] = alpha;
                sm.m_s[row]  = mnew;
                sm.l_s[row]  = sm.l_s[row] * alpha + ssum;
            }
        }
        __syncthreads();

        // ---- O = O*alpha + P @ V via mma (per warp: m16 x n64, K=64) ----
        {
            float alr0 = sm.al_s[qw + (lane >> 2)];
            float alr1 = sm.al_s[qw + (lane >> 2) + 8];
            #pragma unroll
            for (int nt = 0; nt < 8; ++nt) {
                o[nt][0] *= alr0; o[nt][1] *= alr0;
                o[nt][2] *= alr1; o[nt][3] *= alr1;
            }
            #pragma unroll
            for (int ks = 0; ks < 8; ++ks) {
                uint32_t afr[4];
                const float* ap = &sm.Ps[qw + (lane >> 2)][ks * 8 + (lane & 3)];
                afr[0] = f2tf(ap[0]);
                afr[1] = f2tf(ap[8 * PPAD]);
                afr[2] = f2tf(ap[4]);
                afr[3] = f2tf(ap[8 * PPAD + 4]);
                #pragma unroll
                for (int nt = 0; nt < 8; ++nt) {
                    const float* bp = &sm.Vs[ks * 8 + (lane & 3)][dw + nt * 8 + (lane >> 2)];
                    uint32_t bfr[2] = { __float_as_uint(bp[0]), __float_as_uint(bp[4 * VPAD]) };
                    MMA_TF32(o[nt], afr, bfr);
                }
            }
        }
    }

    // ---- epilogue: divide by l, write ctx ----
    __syncthreads();
    {
        float li0 = 1.f / sm.l_s[qw + (lane >> 2)];
        float li1 = 1.f / sm.l_s[qw + (lane >> 2) + 8];
        int r0 = t0 + qw + (lane >> 2);
        #pragma unroll
        for (int nt = 0; nt < 8; ++nt) {
            int cc = dw + nt * 8 + (lane & 3) * 2;
            *(float2*)&g_ctx[((size_t)r0 * H_ + h) * D_ + cc] =
                make_float2(o[nt][0] * li0, o[nt][1] * li0);
            *(float2*)&g_ctx[((size_t)(r0 + 8) * H_ + h) * D_ + cc] =
                make_float2(o[nt][2] * li1, o[nt][3] * li1);
        }
    }
}

// ============================================================================
// launch
// ============================================================================
extern "C" void kernel_launch(void* const* d_in, const int* in_sizes, int n_in,
                              void* d_out, int out_size)
{
    (void)in_sizes; (void)n_in; (void)out_size;
    const float* hs   = (const float*)d_in[0];
    const float* cosb = (const float*)d_in[1];
    const float* sinb = (const float*)d_in[2];
    const float* wqkv = (const float*)d_in[3];
    const float* qw   = (const float*)d_in[4];
    const float* kw   = (const float*)d_in[5];
    const float* wo   = (const float*)d_in[6];
    float* out = (float*)d_out;

    float *qkv_p, *ctx_p, *wqkvT_p, *woT_p;
    cudaGetSymbolAddress((void**)&qkv_p,   g_qkv);
    cudaGetSymbolAddress((void**)&ctx_p,   g_ctx);
    cudaGetSymbolAddress((void**)&wqkvT_p, g_wqkvT);
    cudaGetSymbolAddress((void**)&woT_p,   g_woT);

    static int configured = -1;
    if (configured < 0) {
        cudaFuncSetAttribute(mma_gemm_kernel, cudaFuncAttributeMaxDynamicSharedMemorySize, GEMM_SMEM);
        cudaFuncSetAttribute(attn_kernel, cudaFuncAttributeMaxDynamicSharedMemorySize, (int)sizeof(AttnSmem));
        configured = 1;
    }

    // 0) transpose weights to [N, K] K-major (B operand wants K contiguous)
    transpose_kernel<<<dim3(NQKV_ / 32, HID_ / 32), dim3(32, 8)>>>(wqkv, wqkvT_p, HID_, NQKV_);
    transpose_kernel<<<dim3(HID_ / 32, (H_ * D_) / 32), dim3(32, 8)>>>(wo, woT_p, H_ * D_, HID_);

    // 1) qkv = hidden @ w_qkv   (tf32 mma)
    mma_gemm_kernel<<<dim3(NQKV_ / 128, BS_ / 128), 256, GEMM_SMEM>>>(BS_, NQKV_, HID_, hs, wqkvT_p, qkv_p);

    // 2) per-head RMSNorm + RoPE
    normrope_kernel<<<dim3(BS_, H_ + HK_), 128>>>(cosb, sinb, qw, kw);

    // 3) GQA causal flash attention -> g_ctx  (tf32 mma)
    attn_kernel<<<dim3(S_ / ABM, H_, B_), 256, sizeof(AttnSmem)>>>();

    // 4) out = ctx @ w_o        (tf32 mma)
    mma_gemm_kernel<<<dim3(HID_ / 128, BS_ / 128), 256, GEMM_SMEM>>>(BS_, HID_, H_ * D_, ctx_p, woT_p, out);
}

// round 14
// speedup vs baseline: 2.1739x; 1.0197x over previous
#include <cuda_runtime.h>
#include <cuda_bf16.h>
#include <cstdint>

// ---------------- problem constants ----------------
#define B_    2
#define S_    1024
#define HID_  2048
#define H_    32
#define HK_   4
#define D_    128
#define G_    (H_ / HK_)              // 8
#define NQKV_ ((H_ + 2 * HK_) * D_)   // 5120
#define BS_   (B_ * S_)               // 2048
#define EPS_  1e-6f
#define SCALE_ 0.08838834764831845f   // 1/sqrt(128)

// ---------------- scratch (static device memory; no allocs allowed) ----------------
__device__ float g_qkv  [(size_t)BS_ * NQKV_];        // [2048, 5120]
__device__ float g_q    [(size_t)BS_ * H_  * D_];     // [2048, 32, 128]
__device__ float g_k    [(size_t)BS_ * HK_ * D_];     // [2048, 4, 128]
__device__ float g_ctx  [(size_t)BS_ * H_  * D_];     // [2048, 4096]

extern __shared__ char dyn_smem[];

// ---------------- helpers ----------------
__device__ __forceinline__ uint32_t f2tf(float x) {   // round-to-nearest tf32
    uint32_t r;
    asm("cvt.rna.tf32.f32 %0, %1;" : "=r"(r) : "f"(x));
    return r;
}
__device__ __forceinline__ float tf2f(float x) { return __uint_as_float(f2tf(x)); }

// mma.sync m16n8k8 tf32: D(f32) = A(tf32,row) * B(tf32,col) + D
#define MMA_TF32(c, a, b)                                                      \
    asm volatile(                                                              \
        "mma.sync.aligned.m16n8k8.row.col.f32.tf32.tf32.f32 "                  \
        "{%0,%1,%2,%3}, {%4,%5,%6,%7}, {%8,%9}, {%0,%1,%2,%3};"                \
        : "+f"((c)[0]), "+f"((c)[1]), "+f"((c)[2]), "+f"((c)[3])               \
        : "r"((a)[0]), "r"((a)[1]), "r"((a)[2]), "r"((a)[3]),                  \
          "r"((b)[0]), "r"((b)[1]))

// Fragment layouts (lane = threadIdx.x & 31):
//  A m16k8: a0=(r,c) a1=(r+8,c) a2=(r,c+4) a3=(r+8,c+4), r=lane>>2, c=lane&3
//  B k8n8 : b0=(k,n) b1=(k+4,n),                         k=lane&3, n=lane>>2
//  C m16n8: c0=(r,2t) c1=(r,2t+1) c2=(r+8,2t) c3=(r+8,2t+1), t=lane&3

// ============================================================================
// tf32 tensor-core GEMM: C[M,N] = A[M,K] @ B[K,N]   (both row-major, as given)
// 128x128 CTA tile, BK=32, 256 threads (8 warps in 2Mx4N), reg-prefetch DB.
// A smem: [128][36] (m-major, K-contig, pad 36). B smem: [32][136] (k rows,
// n-contig, pad 136) filled straight from [K,N] -> NO weight transpose needed.
// Frag-load banks: A: 4r+c+... distinct; B: 8c+q+8nt distinct. Conflict-free.
// ============================================================================
#define SROW 36
#define BROW 136
#define GEMM_SMEM ((2 * 128 * SROW + 2 * 32 * BROW) * 4)   // 71680 B

__global__ __launch_bounds__(256, 1)
void mma_gemm_kernel(int M, int N, int K,
                     const float* __restrict__ A,
                     const float* __restrict__ Bm,
                     float* __restrict__ C)
{
    float* sm = (float*)dyn_smem;
    float* Asm[2] = { sm,                  sm + 128 * SROW };
    float* Bsm[2] = { sm + 2 * 128 * SROW, sm + 2 * 128 * SROW + 32 * BROW };

    const int tid  = threadIdx.x;
    const int lane = tid & 31;
    const int wid  = tid >> 5;
    const int wm   = (wid & 1) * 64;    // warp M offset
    const int wn   = (wid >> 1) * 32;   // warp N offset
    const int m0 = blockIdx.y * 128;
    const int n0 = blockIdx.x * 128;

    float acc[4][4][4];
    #pragma unroll
    for (int i = 0; i < 4; i++)
        #pragma unroll
        for (int j = 0; j < 4; j++)
            #pragma unroll
            for (int r = 0; r < 4; r++) acc[i][j][r] = 0.f;

    const int ntc = K >> 5;

    // ---- preload chunk 0 ----
    #pragma unroll
    for (int i = 0; i < 4; ++i) {
        int lin = i * 256 + tid;          // 0..1023
        // A: row = lin>>3 (0..127), 4 cols of K
        int arow = lin >> 3;
        int ac4  = (lin & 7) * 4;
        float4 va = *(const float4*)(A + (size_t)(m0 + arow) * K + ac4);
        float* pa = Asm[0] + arow * SROW + ac4;
        pa[0] = tf2f(va.x); pa[1] = tf2f(va.y); pa[2] = tf2f(va.z); pa[3] = tf2f(va.w);
        // B: k-row = lin>>5 (0..31), 4 cols of N
        int kk = lin >> 5;
        int n4 = (lin & 31) * 4;
        float4 vb = *(const float4*)(Bm + (size_t)kk * N + n0 + n4);
        float* pb = Bsm[0] + kk * BROW + n4;
        pb[0] = tf2f(vb.x); pb[1] = tf2f(vb.y); pb[2] = tf2f(vb.z); pb[3] = tf2f(vb.w);
    }
    __syncthreads();

    for (int t = 0; t < ntc; ++t) {
        const int buf = t & 1;
        float4 pfa[4], pfb[4];
        if (t + 1 < ntc) {
            const int k0 = (t + 1) << 5;
            #pragma unroll
            for (int i = 0; i < 4; ++i) {
                int lin = i * 256 + tid;
                int arow = lin >> 3;
                int ac4  = (lin & 7) * 4;
                pfa[i] = *(const float4*)(A + (size_t)(m0 + arow) * K + k0 + ac4);
                int kk = lin >> 5;
                int n4 = (lin & 31) * 4;
                pfb[i] = *(const float4*)(Bm + (size_t)(k0 + kk) * N + n0 + n4);
            }
        }

        // ---- compute chunk: 4 k-steps of 8 ----
        const float* Ab = Asm[buf];
        const float* Bb = Bsm[buf];
        #pragma unroll
        for (int ks = 0; ks < 4; ++ks) {
            uint32_t afr[4][4];
            #pragma unroll
            for (int mt = 0; mt < 4; ++mt) {
                const float* ap = Ab + (wm + mt * 16 + (lane >> 2)) * SROW + ks * 8 + (lane & 3);
                afr[mt][0] = __float_as_uint(ap[0]);
                afr[mt][1] = __float_as_uint(ap[8 * SROW]);
                afr[mt][2] = __float_as_uint(ap[4]);
                afr[mt][3] = __float_as_uint(ap[8 * SROW + 4]);
            }
            uint32_t bfr[4][2];
            #pragma unroll
            for (int nt = 0; nt < 4; ++nt) {
                // B frag: b0=(k,n), b1=(k+4,n); Bsm is [k][n] n-contig
                const float* bp = Bb + (ks * 8 + (lane & 3)) * BROW + wn + nt * 8 + (lane >> 2);
                bfr[nt][0] = __float_as_uint(bp[0]);
                bfr[nt][1] = __float_as_uint(bp[4 * BROW]);
            }
            #pragma unroll
            for (int mt = 0; mt < 4; ++mt)
                #pragma unroll
                for (int nt = 0; nt < 4; ++nt)
                    MMA_TF32(acc[mt][nt], afr[mt], bfr[nt]);
        }

        if (t + 1 < ntc) {
            #pragma unroll
            for (int i = 0; i < 4; ++i) {
                int lin = i * 256 + tid;
                int arow = lin >> 3;
                int ac4  = (lin & 7) * 4;
                float* pa = Asm[buf ^ 1] + arow * SROW + ac4;
                pa[0] = tf2f(pfa[i].x); pa[1] = tf2f(pfa[i].y); pa[2] = tf2f(pfa[i].z); pa[3] = tf2f(pfa[i].w);
                int kk = lin >> 5;
                int n4 = (lin & 31) * 4;
                float* pb = Bsm[buf ^ 1] + kk * BROW + n4;
                pb[0] = tf2f(pfb[i].x); pb[1] = tf2f(pfb[i].y); pb[2] = tf2f(pfb[i].z); pb[3] = tf2f(pfb[i].w);
            }
        }
        __syncthreads();
    }

    // ---- epilogue ----
    #pragma unroll
    for (int mt = 0; mt < 4; ++mt) {
        #pragma unroll
        for (int nt = 0; nt < 4; ++nt) {
            int r0 = m0 + wm + mt * 16 + (lane >> 2);
            int cc = n0 + wn + nt * 8 + (lane & 3) * 2;
            *(float2*)(C + (size_t)r0 * N + cc)       = make_float2(acc[mt][nt][0], acc[mt][nt][1]);
            *(float2*)(C + (size_t)(r0 + 8) * N + cc) = make_float2(acc[mt][nt][2], acc[mt][nt][3]);
        }
    }
}

// ============================================================================
// Fused per-head RMSNorm + RoPE for q and k heads.
// ============================================================================
__global__ __launch_bounds__(128)
void normrope_kernel(const float* __restrict__ cosb,
                     const float* __restrict__ sinb,
                     const float* __restrict__ qw,
                     const float* __restrict__ kw)
{
    const int t  = blockIdx.x;
    const int hh = blockIdx.y;
    const int d  = threadIdx.x;
    const int s  = t & (S_ - 1);

    const float* src;
    const float* w;
    float* dst;
    if (hh < H_) {
        src = g_qkv + (size_t)t * NQKV_ + hh * D_;
        w   = qw;
        dst = g_q + ((size_t)t * H_ + hh) * D_;
    } else {
        int kh = hh - H_;
        src = g_qkv + (size_t)t * NQKV_ + (H_ + kh) * D_;
        w   = kw;
        dst = g_k + ((size_t)t * HK_ + kh) * D_;
    }

    float x = src[d];
    float v = x * x;
    #pragma unroll
    for (int o = 16; o > 0; o >>= 1)
        v += __shfl_xor_sync(0xffffffffu, v, o);

    __shared__ float red[4];
    __shared__ float xn_s[D_];
    int warp = d >> 5, lane = d & 31;
    if (lane == 0) red[warp] = v;
    __syncthreads();
    float total = red[0] + red[1] + red[2] + red[3];
    float xn = w[d] * x * rsqrtf(total * (1.0f / D_) + EPS_);
    xn_s[d] = xn;
    __syncthreads();
    float other = (d < 64) ? xn_s[d + 64] : xn_s[d - 64];
    float rot   = (d < 64) ? -other : other;
    dst[d] = xn * cosb[s * D_ + d] + rot * sinb[s * D_ + d];
}

// ============================================================================
// Flash attention (causal, GQA) with tf32 mma.sync matmuls + fp32 softmax.
// One block = 64 q rows of one (b, h). 256 threads = 8 warps.
//   S phase: warp (qw=wid&3, kvw=wid>>2): S tile m16(q) x n32(kv), K=128.
//   PV phase: warp (qw=wid&3, dw=wid>>2): O tile m16(q) x n64(d), K=64.
// Q/K: stride 128, XOR swizzle col^=(row&7)<<2 (16B groups). V: stride 128,
// swizzle col^=(row&7)<<3 (32B groups). P: pad 68. All frag LDS conflict-free.
// Smem = 116,480 B -> 2 CTAs/SM (was 120.4 KB -> 1 CTA/SM).
// ============================================================================
#define ABM 64
#define ABN 64
#define PPAD 68

struct AttnSmem {
    float Qs[ABM][128];
    float Ks[ABN][128];
    float Vs[ABN][128];
    float Ps[ABM][PPAD];
    float m_s[ABM];
    float l_s[ABM];
    float al_s[ABM];
};

__global__ __launch_bounds__(256, 1)
void attn_kernel()
{
    AttnSmem& sm = *reinterpret_cast<AttnSmem*>(dyn_smem);
    const int tid  = threadIdx.x;
    const int lane = tid & 31;
    const int wid  = tid >> 5;
    const int qw   = (wid & 3) * 16;    // q-row group (shared by S and PV phases)
    const int kvw  = (wid >> 2) * 32;   // kv-col group (S phase)
    const int dw   = (wid >> 2) * 64;   // d-col group (PV phase)

    const int qt = blockIdx.x;
    const int h  = blockIdx.y;
    const int b  = blockIdx.z;
    const int kh = h / G_;
    const int t0 = b * S_ + qt * ABM;

    const int lr = lane >> 2;           // 0..7
    const int lc = lane & 3;            // 0..3

    // ---- load Q tile (swizzled, tf32-rounded) ----
    #pragma unroll
    for (int it = 0; it < 8; ++it) {
        int lin = it * 256 + tid;        // 0..2047
        int r   = lin >> 5;              // 0..63
        int d4  = (lin & 31) << 2;
        float4 v = *(const float4*)&g_q[((size_t)(t0 + r) * H_ + h) * D_ + d4];
        *(float4*)&sm.Qs[r][d4 ^ ((r & 7) << 2)] =
            make_float4(tf2f(v.x), tf2f(v.y), tf2f(v.z), tf2f(v.w));
    }
    if (tid < ABM) { sm.m_s[tid] = -1e30f; sm.l_s[tid] = 0.f; }

    float o[8][4];
    #pragma unroll
    for (int i = 0; i < 8; i++)
        #pragma unroll
        for (int j = 0; j < 4; j++) o[i][j] = 0.f;

    for (int j = 0; j <= qt; ++j) {
        __syncthreads();   // Q visible (j==0); prev PV reads done before K/V/P overwrite

        // ---- load K, V tiles (swizzled, tf32-rounded) ----
        const int kt0 = b * S_ + j * ABN;
        #pragma unroll
        for (int it = 0; it < 8; ++it) {
            int lin = it * 256 + tid;
            int r   = lin >> 5;
            int d4  = (lin & 31) << 2;
            float4 kv = *(const float4*)&g_k[((size_t)(kt0 + r) * HK_ + kh) * D_ + d4];
            *(float4*)&sm.Ks[r][d4 ^ ((r & 7) << 2)] =
                make_float4(tf2f(kv.x), tf2f(kv.y), tf2f(kv.z), tf2f(kv.w));
            float4 vv = *(const float4*)&g_qkv[(size_t)(kt0 + r) * NQKV_ + (H_ + HK_) * D_ + kh * D_ + d4];
            *(float4*)&sm.Vs[r][d4 ^ ((r & 7) << 3)] =
                make_float4(tf2f(vv.x), tf2f(vv.y), tf2f(vv.z), tf2f(vv.w));
        }
        __syncthreads();

        // ---- S = Q @ K^T via mma (per warp: m16 x n32, K=128) ----
        float s[4][4];
        #pragma unroll
        for (int nt = 0; nt < 4; ++nt)
            #pragma unroll
            for (int r = 0; r < 4; ++r) s[nt][r] = 0.f;

        #pragma unroll
        for (int ks = 0; ks < 16; ++ks) {
            uint32_t afr[4];
            {
                int sc = (ks * 8 + lc) ^ (lr << 2);   // row&7 == lr for both r and r+8
                const float* r0p = sm.Qs[qw + lr];
                const float* r1p = sm.Qs[qw + lr + 8];
                afr[0] = __float_as_uint(r0p[sc]);
                afr[1] = __float_as_uint(r1p[sc]);
                afr[2] = __float_as_uint(r0p[sc ^ 4]);
                afr[3] = __float_as_uint(r1p[sc ^ 4]);
            }
            #pragma unroll
            for (int nt = 0; nt < 4; ++nt) {
                int sc = (ks * 8 + lc) ^ (lr << 2);
                const float* bp = sm.Ks[kvw + nt * 8 + lr];
                uint32_t bfr[2] = { __float_as_uint(bp[sc]), __float_as_uint(bp[sc ^ 4]) };
                MMA_TF32(s[nt], afr, bfr);
            }
        }

        // ---- write S to Ps with scale + causal mask ----
        const bool diag = (j == qt);
        const int sr = qw + lr;
        #pragma unroll
        for (int nt = 0; nt < 4; ++nt) {
            int cc = kvw + nt * 8 + lc * 2;
            float v0 = s[nt][0] * SCALE_;
            float v1 = s[nt][1] * SCALE_;
            float v2 = s[nt][2] * SCALE_;
            float v3 = s[nt][3] * SCALE_;
            if (diag) {
                if (cc     > sr)     v0 = -1e30f;
                if (cc + 1 > sr)     v1 = -1e30f;
                if (cc     > sr + 8) v2 = -1e30f;
                if (cc + 1 > sr + 8) v3 = -1e30f;
            }
            sm.Ps[sr][cc]     = v0;
            sm.Ps[sr][cc + 1] = v1;
            sm.Ps[sr + 8][cc]     = v2;
            sm.Ps[sr + 8][cc + 1] = v3;
        }
        __syncthreads();

        // ---- online softmax (4 threads per row), fp32 ----
        {
            int row = tid >> 2, q4 = tid & 3;
            float vals[16];
            float mloc = -1e30f;
            #pragma unroll
            for (int kk = 0; kk < 16; kk++) {
                vals[kk] = sm.Ps[row][q4 * 16 + kk];
                mloc = fmaxf(mloc, vals[kk]);
            }
            mloc = fmaxf(mloc, __shfl_xor_sync(0xffffffffu, mloc, 1));
            mloc = fmaxf(mloc, __shfl_xor_sync(0xffffffffu, mloc, 2));
            float mold = sm.m_s[row];
            float mnew = fmaxf(mold, mloc);
            float ssum = 0.f;
            #pragma unroll
            for (int kk = 0; kk < 16; kk++) {
                float p = __expf(vals[kk] - mnew);
                sm.Ps[row][q4 * 16 + kk] = p;
                ssum += p;
            }
            ssum += __shfl_xor_sync(0xffffffffu, ssum, 1);
            ssum += __shfl_xor_sync(0xffffffffu, ssum, 2);
            if (q4 == 0) {
                float alpha = __expf(mold - mnew);
                sm.al_s[row] = alpha;
                sm.m_s[row]  = mnew;
                sm.l_s[row]  = sm.l_s[row] * alpha + ssum;
            }
        }
        __syncthreads();

        // ---- O = O*alpha + P @ V via mma (per warp: m16 x n64, K=64) ----
        {
            float alr0 = sm.al_s[qw + lr];
            float alr1 = sm.al_s[qw + lr + 8];
            #pragma unroll
            for (int nt = 0; nt < 8; ++nt) {
                o[nt][0] *= alr0; o[nt][1] *= alr0;
                o[nt][2] *= alr1; o[nt][3] *= alr1;
            }
            #pragma unroll
            for (int ks = 0; ks < 8; ++ks) {
                uint32_t afr[4];
                const float* ap = &sm.Ps[qw + lr][ks * 8 + lc];
                afr[0] = f2tf(ap[0]);
                afr[1] = f2tf(ap[8 * PPAD]);
                afr[2] = f2tf(ap[4]);
                afr[3] = f2tf(ap[8 * PPAD + 4]);
                #pragma unroll
                for (int nt = 0; nt < 8; ++nt) {
                    // V frag: b0=(k,n), b1=(k+4,n); k&7 = lc, (k+4)&7 = lc+4
                    int n  = dw + nt * 8 + lr;
                    int sc = n ^ (lc << 3);
                    const float* b0p = sm.Vs[ks * 8 + lc];
                    const float* b1p = sm.Vs[ks * 8 + lc + 4];
                    uint32_t bfr[2] = { __float_as_uint(b0p[sc]),
                                        __float_as_uint(b1p[sc ^ 32]) };
                    MMA_TF32(o[nt], afr, bfr);
                }
            }
        }
    }

    // ---- epilogue: divide by l, write ctx ----
    __syncthreads();
    {
        float li0 = 1.f / sm.l_s[qw + lr];
        float li1 = 1.f / sm.l_s[qw + lr + 8];
        int r0 = t0 + qw + lr;
        #pragma unroll
        for (int nt = 0; nt < 8; ++nt) {
            int cc = dw + nt * 8 + lc * 2;
            *(float2*)&g_ctx[((size_t)r0 * H_ + h) * D_ + cc] =
                make_float2(o[nt][0] * li0, o[nt][1] * li0);
            *(float2*)&g_ctx[((size_t)(r0 + 8) * H_ + h) * D_ + cc] =
                make_float2(o[nt][2] * li1, o[nt][3] * li1);
        }
    }
}

// ============================================================================
// launch
// ============================================================================
extern "C" void kernel_launch(void* const* d_in, const int* in_sizes, int n_in,
                              void* d_out, int out_size)
{
    (void)in_sizes; (void)n_in; (void)out_size;
    const float* hs   = (const float*)d_in[0];
    const float* cosb = (const float*)d_in[1];
    const float* sinb = (const float*)d_in[2];
    const float* wqkv = (const float*)d_in[3];
    const float* qw   = (const float*)d_in[4];
    const float* kw   = (const float*)d_in[5];
    const float* wo   = (const float*)d_in[6];
    float* out = (float*)d_out;

    float *qkv_p, *ctx_p;
    cudaGetSymbolAddress((void**)&qkv_p, g_qkv);
    cudaGetSymbolAddress((void**)&ctx_p, g_ctx);

    static int configured = -1;
    if (configured < 0) {
        cudaFuncSetAttribute(mma_gemm_kernel, cudaFuncAttributeMaxDynamicSharedMemorySize, GEMM_SMEM);
        cudaFuncSetAttribute(attn_kernel, cudaFuncAttributeMaxDynamicSharedMemorySize, (int)sizeof(AttnSmem));
        configured = 1;
    }

    // 1) qkv = hidden @ w_qkv   (tf32 mma, B read directly from [K,N])
    mma_gemm_kernel<<<dim3(NQKV_ / 128, BS_ / 128), 256, GEMM_SMEM>>>(BS_, NQKV_, HID_, hs, wqkv, qkv_p);

    // 2) per-head RMSNorm + RoPE
    normrope_kernel<<<dim3(BS_, H_ + HK_), 128>>>(cosb, sinb, qw, kw);

    // 3) GQA causal flash attention -> g_ctx  (tf32 mma)
    attn_kernel<<<dim3(S_ / ABM, H_, B_), 256, sizeof(AttnSmem)>>>();

    // 4) out = ctx @ w_o        (tf32 mma, B read directly from [K,N])
    mma_gemm_kernel<<<dim3(HID_ / 128, BS_ / 128), 256, GEMM_SMEM>>>(BS_, HID_, H_ * D_, ctx_p, wo, out);
}

// round 15
// speedup vs baseline: 3.1930x; 1.4688x over previous
#include <cuda_runtime.h>
#include <cuda_bf16.h>
#include <cstdint>

// ---------------- problem constants ----------------
#define B_    2
#define S_    1024
#define HID_  2048
#define H_    32
#define HK_   4
#define D_    128
#define G_    (H_ / HK_)              // 8
#define NQKV_ ((H_ + 2 * HK_) * D_)   // 5120
#define BS_   (B_ * S_)               // 2048
#define EPS_  1e-6f
#define SCALE_ 0.08838834764831845f   // 1/sqrt(128)

// ---------------- scratch (static device memory; no allocs allowed) ----------------
__device__ float g_qkv  [(size_t)BS_ * NQKV_];        // [2048, 5120]
__device__ float g_q    [(size_t)BS_ * H_  * D_];     // [2048, 32, 128]
__device__ float g_k    [(size_t)BS_ * HK_ * D_];     // [2048, 4, 128]
__device__ float g_ctx  [(size_t)BS_ * H_  * D_];     // [2048, 4096]

extern __shared__ char dyn_smem[];

// ---------------- helpers ----------------
__device__ __forceinline__ uint32_t smem_u32(const void* p) {
    uint32_t a;
    asm("{ .reg .u64 t; cvta.to.shared.u64 t, %1; cvt.u32.u64 %0, t; }" : "=r"(a) : "l"(p));
    return a;
}
__device__ __forceinline__ uint32_t f2tf(float x) {   // round-to-nearest tf32
    uint32_t r;
    asm("cvt.rna.tf32.f32 %0, %1;" : "=r"(r) : "f"(x));
    return r;
}
__device__ __forceinline__ float tf2f(float x) { return __uint_as_float(f2tf(x)); }

__device__ __forceinline__ void cp16(uint32_t saddr, const void* gptr) {
    asm volatile("cp.async.cg.shared.global [%0], [%1], 16;" :: "r"(saddr), "l"(gptr) : "memory");
}
#define CP_COMMIT() asm volatile("cp.async.commit_group;" ::: "memory")
#define CP_WAIT1()  asm volatile("cp.async.wait_group 1;" ::: "memory")

// mma.sync m16n8k8 tf32: D(f32) = A(tf32,row) * B(tf32,col) + D
#define MMA_TF32(c, a, b)                                                      \
    asm volatile(                                                              \
        "mma.sync.aligned.m16n8k8.row.col.f32.tf32.tf32.f32 "                  \
        "{%0,%1,%2,%3}, {%4,%5,%6,%7}, {%8,%9}, {%0,%1,%2,%3};"                \
        : "+f"((c)[0]), "+f"((c)[1]), "+f"((c)[2]), "+f"((c)[3])               \
        : "r"((a)[0]), "r"((a)[1]), "r"((a)[2]), "r"((a)[3]),                  \
          "r"((b)[0]), "r"((b)[1]))

// Fragment layouts (lane = threadIdx.x & 31):
//  A m16k8: a0=(r,c) a1=(r+8,c) a2=(r,c+4) a3=(r+8,c+4), r=lane>>2, c=lane&3
//  B k8n8 : b0=(k,n) b1=(k+4,n),                         k=lane&3, n=lane>>2
//  C m16n8: c0=(r,2t) c1=(r,2t+1) c2=(r+8,2t) c3=(r+8,2t+1), t=lane&3

// ============================================================================
// tf32 tensor-core GEMM: C[M,N] = A[M,K] @ B[K,N]   (both row-major, as given)
// 128x128 CTA tile, BK=32, 256 threads (8 warps in 2Mx4N).
// 3-stage cp.async pipeline (gmem->smem async, overlapped with MMA).
// A smem: [128][36] fp32 raw. B smem: [32][136] fp32 raw (straight from [K,N]).
// fp32->tf32 cvt.rna applied at fragment load (numerically identical to
// converting at store: same value, same rounding). Frag LDS conflict-free.
// ============================================================================
#define SROW 36
#define BROW 136
#define ASTG (128 * SROW)              // floats per A stage
#define BSTG (32 * BROW)               // floats per B stage
#define STG  (ASTG + BSTG)
#define NSTAGE 3
#define GEMM_SMEM (NSTAGE * STG * 4)   // 107,520 B

__global__ __launch_bounds__(256, 1)
void mma_gemm_kernel(int M, int N, int K,
                     const float* __restrict__ A,
                     const float* __restrict__ Bm,
                     float* __restrict__ C)
{
    float* sm = (float*)dyn_smem;
    const uint32_t sbase = smem_u32(sm);

    const int tid  = threadIdx.x;
    const int lane = tid & 31;
    const int wid  = tid >> 5;
    const int wm   = (wid & 1) * 64;    // warp M offset
    const int wn   = (wid >> 1) * 32;   // warp N offset
    const int m0 = blockIdx.y * 128;
    const int n0 = blockIdx.x * 128;

    const int ntc = K >> 5;

    // per-thread load indices (4 x 16B for A, 4 x 16B for B per stage)
    const int arow = tid >> 1;                 // unused split; use lin scheme below

    (void)arow;

    float acc[4][4][4];
    #pragma unroll
    for (int i = 0; i < 4; i++)
        #pragma unroll
        for (int j = 0; j < 4; j++)
            #pragma unroll
            for (int r = 0; r < 4; r++) acc[i][j][r] = 0.f;

    // ---- async stage issue ----
    auto issue_stage = [&](int t, int s) {
        const int k0 = t << 5;
        const uint32_t abase = sbase + (uint32_t)(s * STG) * 4u;
        const uint32_t bbase = abase + (uint32_t)ASTG * 4u;
        #pragma unroll
        for (int i = 0; i < 4; ++i) {
            int lin = i * 256 + tid;           // 0..1023
            int ar  = lin >> 3;                // 0..127
            int ac4 = (lin & 7) * 4;           // 0..28
            cp16(abase + (uint32_t)(ar * SROW + ac4) * 4u,
                 A + (size_t)(m0 + ar) * K + k0 + ac4);
            int kk = lin >> 5;                 // 0..31
            int n4 = (lin & 31) * 4;           // 0..124
            cp16(bbase + (uint32_t)(kk * BROW + n4) * 4u,
                 Bm + (size_t)(k0 + kk) * N + n0 + n4);
        }
        CP_COMMIT();
    };

    issue_stage(0, 0);
    issue_stage(1, 1);

    for (int t = 0; t < ntc; ++t) {
        CP_WAIT1();          // stage t resident (newest pending group may still fly)
        __syncthreads();

        // issue next stage (or empty group to keep wait_group accounting uniform)
        if (t + 2 < ntc) issue_stage(t + 2, (t + 2) % NSTAGE);
        else             CP_COMMIT();

        // ---- compute stage t ----
        const float* Ab = sm + (t % NSTAGE) * STG;
        const float* Bb = Ab + ASTG;
        #pragma unroll
        for (int ks = 0; ks < 4; ++ks) {
            uint32_t afr[4][4];
            #pragma unroll
            for (int mt = 0; mt < 4; ++mt) {
                const float* ap = Ab + (wm + mt * 16 + (lane >> 2)) * SROW + ks * 8 + (lane & 3);
                afr[mt][0] = f2tf(ap[0]);
                afr[mt][1] = f2tf(ap[8 * SROW]);
                afr[mt][2] = f2tf(ap[4]);
                afr[mt][3] = f2tf(ap[8 * SROW + 4]);
            }
            uint32_t bfr[4][2];
            #pragma unroll
            for (int nt = 0; nt < 4; ++nt) {
                const float* bp = Bb + (ks * 8 + (lane & 3)) * BROW + wn + nt * 8 + (lane >> 2);
                bfr[nt][0] = f2tf(bp[0]);
                bfr[nt][1] = f2tf(bp[4 * BROW]);
            }
            #pragma unroll
            for (int mt = 0; mt < 4; ++mt)
                #pragma unroll
                for (int nt = 0; nt < 4; ++nt)
                    MMA_TF32(acc[mt][nt], afr[mt], bfr[nt]);
        }
        __syncthreads();     // all warps done with stage t before it is refilled
    }

    // ---- epilogue ----
    #pragma unroll
    for (int mt = 0; mt < 4; ++mt) {
        #pragma unroll
        for (int nt = 0; nt < 4; ++nt) {
            int r0 = m0 + wm + mt * 16 + (lane >> 2);
            int cc = n0 + wn + nt * 8 + (lane & 3) * 2;
            *(float2*)(C + (size_t)r0 * N + cc)       = make_float2(acc[mt][nt][0], acc[mt][nt][1]);
            *(float2*)(C + (size_t)(r0 + 8) * N + cc) = make_float2(acc[mt][nt][2], acc[mt][nt][3]);
        }
    }
}

// ============================================================================
// Fused per-head RMSNorm + RoPE for q and k heads.
// ============================================================================
__global__ __launch_bounds__(128)
void normrope_kernel(const float* __restrict__ cosb,
                     const float* __restrict__ sinb,
                     const float* __restrict__ qw,
                     const float* __restrict__ kw)
{
    const int t  = blockIdx.x;
    const int hh = blockIdx.y;
    const int d  = threadIdx.x;
    const int s  = t & (S_ - 1);

    const float* src;
    const float* w;
    float* dst;
    if (hh < H_) {
        src = g_qkv + (size_t)t * NQKV_ + hh * D_;
        w   = qw;
        dst = g_q + ((size_t)t * H_ + hh) * D_;
    } else {
        int kh = hh - H_;
        src = g_qkv + (size_t)t * NQKV_ + (H_ + kh) * D_;
        w   = kw;
        dst = g_k + ((size_t)t * HK_ + kh) * D_;
    }

    float x = src[d];
    float v = x * x;
    #pragma unroll
    for (int o = 16; o > 0; o >>= 1)
        v += __shfl_xor_sync(0xffffffffu, v, o);

    __shared__ float red[4];
    __shared__ float xn_s[D_];
    int warp = d >> 5, lane = d & 31;
    if (lane == 0) red[warp] = v;
    __syncthreads();
    float total = red[0] + red[1] + red[2] + red[3];
    float xn = w[d] * x * rsqrtf(total * (1.0f / D_) + EPS_);
    xn_s[d] = xn;
    __syncthreads();
    float other = (d < 64) ? xn_s[d + 64] : xn_s[d - 64];
    float rot   = (d < 64) ? -other : other;
    dst[d] = xn * cosb[s * D_ + d] + rot * sinb[s * D_ + d];
}

// ============================================================================
// Flash attention (causal, GQA) with tf32 mma.sync matmuls + fp32 softmax.
// (unchanged from R14 passing version)
// ============================================================================
#define ABM 64
#define ABN 64
#define PPAD 68

struct AttnSmem {
    float Qs[ABM][128];
    float Ks[ABN][128];
    float Vs[ABN][128];
    float Ps[ABM][PPAD];
    float m_s[ABM];
    float l_s[ABM];
    float al_s[ABM];
};

__global__ __launch_bounds__(256, 1)
void attn_kernel()
{
    AttnSmem& sm = *reinterpret_cast<AttnSmem*>(dyn_smem);
    const int tid  = threadIdx.x;
    const int lane = tid & 31;
    const int wid  = tid >> 5;
    const int qw   = (wid & 3) * 16;    // q-row group
    const int kvw  = (wid >> 2) * 32;   // kv-col group (S phase)
    const int dw   = (wid >> 2) * 64;   // d-col group (PV phase)

    const int qt = blockIdx.x;
    const int h  = blockIdx.y;
    const int b  = blockIdx.z;
    const int kh = h / G_;
    const int t0 = b * S_ + qt * ABM;

    const int lr = lane >> 2;           // 0..7
    const int lc = lane & 3;            // 0..3

    // ---- load Q tile (swizzled, tf32-rounded) ----
    #pragma unroll
    for (int it = 0; it < 8; ++it) {
        int lin = it * 256 + tid;
        int r   = lin >> 5;
        int d4  = (lin & 31) << 2;
        float4 v = *(const float4*)&g_q[((size_t)(t0 + r) * H_ + h) * D_ + d4];
        *(float4*)&sm.Qs[r][d4 ^ ((r & 7) << 2)] =
            make_float4(tf2f(v.x), tf2f(v.y), tf2f(v.z), tf2f(v.w));
    }
    if (tid < ABM) { sm.m_s[tid] = -1e30f; sm.l_s[tid] = 0.f; }

    float o[8][4];
    #pragma unroll
    for (int i = 0; i < 8; i++)
        #pragma unroll
        for (int j = 0; j < 4; j++) o[i][j] = 0.f;

    for (int j = 0; j <= qt; ++j) {
        __syncthreads();

        const int kt0 = b * S_ + j * ABN;
        #pragma unroll
        for (int it = 0; it < 8; ++it) {
            int lin = it * 256 + tid;
            int r   = lin >> 5;
            int d4  = (lin & 31) << 2;
            float4 kv = *(const float4*)&g_k[((size_t)(kt0 + r) * HK_ + kh) * D_ + d4];
            *(float4*)&sm.Ks[r][d4 ^ ((r & 7) << 2)] =
                make_float4(tf2f(kv.x), tf2f(kv.y), tf2f(kv.z), tf2f(kv.w));
            float4 vv = *(const float4*)&g_qkv[(size_t)(kt0 + r) * NQKV_ + (H_ + HK_) * D_ + kh * D_ + d4];
            *(float4*)&sm.Vs[r][d4 ^ ((r & 7) << 3)] =
                make_float4(tf2f(vv.x), tf2f(vv.y), tf2f(vv.z), tf2f(vv.w));
        }
        __syncthreads();

        // ---- S = Q @ K^T ----
        float s[4][4];
        #pragma unroll
        for (int nt = 0; nt < 4; ++nt)
            #pragma unroll
            for (int r = 0; r < 4; ++r) s[nt][r] = 0.f;

        #pragma unroll
        for (int ks = 0; ks < 16; ++ks) {
            uint32_t afr[4];
            {
                int sc = (ks * 8 + lc) ^ (lr << 2);
                const float* r0p = sm.Qs[qw + lr];
                const float* r1p = sm.Qs[qw + lr + 8];
                afr[0] = __float_as_uint(r0p[sc]);
                afr[1] = __float_as_uint(r1p[sc]);
                afr[2] = __float_as_uint(r0p[sc ^ 4]);
                afr[3] = __float_as_uint(r1p[sc ^ 4]);
            }
            #pragma unroll
            for (int nt = 0; nt < 4; ++nt) {
                int sc = (ks * 8 + lc) ^ (lr << 2);
                const float* bp = sm.Ks[kvw + nt * 8 + lr];
                uint32_t bfr[2] = { __float_as_uint(bp[sc]), __float_as_uint(bp[sc ^ 4]) };
                MMA_TF32(s[nt], afr, bfr);
            }
        }

        // ---- scale + causal mask -> Ps ----
        const bool diag = (j == qt);
        const int sr = qw + lr;
        #pragma unroll
        for (int nt = 0; nt < 4; ++nt) {
            int cc = kvw + nt * 8 + lc * 2;
            float v0 = s[nt][0] * SCALE_;
            float v1 = s[nt][1] * SCALE_;
            float v2 = s[nt][2] * SCALE_;
            float v3 = s[nt][3] * SCALE_;
            if (diag) {
                if (cc     > sr)     v0 = -1e30f;
                if (cc + 1 > sr)     v1 = -1e30f;
                if (cc     > sr + 8) v2 = -1e30f;
                if (cc + 1 > sr + 8) v3 = -1e30f;
            }
            sm.Ps[sr][cc]     = v0;
            sm.Ps[sr][cc + 1] = v1;
            sm.Ps[sr + 8][cc]     = v2;
            sm.Ps[sr + 8][cc + 1] = v3;
        }
        __syncthreads();

        // ---- online softmax ----
        {
            int row = tid >> 2, q4 = tid & 3;
            float vals[16];
            float mloc = -1e30f;
            #pragma unroll
            for (int kk = 0; kk < 16; kk++) {
                vals[kk] = sm.Ps[row][q4 * 16 + kk];
                mloc = fmaxf(mloc, vals[kk]);
            }
            mloc = fmaxf(mloc, __shfl_xor_sync(0xffffffffu, mloc, 1));
            mloc = fmaxf(mloc, __shfl_xor_sync(0xffffffffu, mloc, 2));
            float mold = sm.m_s[row];
            float mnew = fmaxf(mold, mloc);
            float ssum = 0.f;
            #pragma unroll
            for (int kk = 0; kk < 16; kk++) {
                float p = __expf(vals[kk] - mnew);
                sm.Ps[row][q4 * 16 + kk] = p;
                ssum += p;
            }
            ssum += __shfl_xor_sync(0xffffffffu, ssum, 1);
            ssum += __shfl_xor_sync(0xffffffffu, ssum, 2);
            if (q4 == 0) {
                float alpha = __expf(mold - mnew);
                sm.al_s[row] = alpha;
                sm.m_s[row]  = mnew;
                sm.l_s[row]  = sm.l_s[row] * alpha + ssum;
            }
        }
        __syncthreads();

        // ---- O = O*alpha + P @ V ----
        {
            float alr0 = sm.al_s[qw + lr];
            float alr1 = sm.al_s[qw + lr + 8];
            #pragma unroll
            for (int nt = 0; nt < 8; ++nt) {
                o[nt][0] *= alr0; o[nt][1] *= alr0;
                o[nt][2] *= alr1; o[nt][3] *= alr1;
            }
            #pragma unroll
            for (int ks = 0; ks < 8; ++ks) {
                uint32_t afr[4];
                const float* ap = &sm.Ps[qw + lr][ks * 8 + lc];
                afr[0] = f2tf(ap[0]);
                afr[1] = f2tf(ap[8 * PPAD]);
                afr[2] = f2tf(ap[4]);
                afr[3] = f2tf(ap[8 * PPAD + 4]);
                #pragma unroll
                for (int nt = 0; nt < 8; ++nt) {
                    int n  = dw + nt * 8 + lr;
                    int sc = n ^ (lc << 3);
                    const float* b0p = sm.Vs[ks * 8 + lc];
                    const float* b1p = sm.Vs[ks * 8 + lc + 4];
                    uint32_t bfr[2] = { __float_as_uint(b0p[sc]),
                                        __float_as_uint(b1p[sc ^ 32]) };
                    MMA_TF32(o[nt], afr, bfr);
                }
            }
        }
    }

    // ---- epilogue ----
    __syncthreads();
    {
        float li0 = 1.f / sm.l_s[qw + lr];
        float li1 = 1.f / sm.l_s[qw + lr + 8];
        int r0 = t0 + qw + lr;
        #pragma unroll
        for (int nt = 0; nt < 8; ++nt) {
            int cc = dw + nt * 8 + lc * 2;
            *(float2*)&g_ctx[((size_t)r0 * H_ + h) * D_ + cc] =
                make_float2(o[nt][0] * li0, o[nt][1] * li0);
            *(float2*)&g_ctx[((size_t)(r0 + 8) * H_ + h) * D_ + cc] =
                make_float2(o[nt][2] * li1, o[nt][3] * li1);
        }
    }
}

// ============================================================================
// launch
// ============================================================================
extern "C" void kernel_launch(void* const* d_in, const int* in_sizes, int n_in,
                              void* d_out, int out_size)
{
    (void)in_sizes; (void)n_in; (void)out_size;
    const float* hs   = (const float*)d_in[0];
    const float* cosb = (const float*)d_in[1];
    const float* sinb = (const float*)d_in[2];
    const float* wqkv = (const float*)d_in[3];
    const float* qw   = (const float*)d_in[4];
    const float* kw   = (const float*)d_in[5];
    const float* wo   = (const float*)d_in[6];
    float* out = (float*)d_out;

    float *qkv_p, *ctx_p;
    cudaGetSymbolAddress((void**)&qkv_p, g_qkv);
    cudaGetSymbolAddress((void**)&ctx_p, g_ctx);

    static int configured = -1;
    if (configured < 0) {
        cudaFuncSetAttribute(mma_gemm_kernel, cudaFuncAttributeMaxDynamicSharedMemorySize, GEMM_SMEM);
        cudaFuncSetAttribute(attn_kernel, cudaFuncAttributeMaxDynamicSharedMemorySize, (int)sizeof(AttnSmem));
        configured = 1;
    }

    // 1) qkv = hidden @ w_qkv   (tf32 mma, cp.async pipeline)
    mma_gemm_kernel<<<dim3(NQKV_ / 128, BS_ / 128), 256, GEMM_SMEM>>>(BS_, NQKV_, HID_, hs, wqkv, qkv_p);

    // 2) per-head RMSNorm + RoPE
    normrope_kernel<<<dim3(BS_, H_ + HK_), 128>>>(cosb, sinb, qw, kw);

    // 3) GQA causal flash attention -> g_ctx  (tf32 mma)
    attn_kernel<<<dim3(S_ / ABM, H_, B_), 256, sizeof(AttnSmem)>>>();

    // 4) out = ctx @ w_o        (tf32 mma, cp.async pipeline)
    mma_gemm_kernel<<<dim3(HID_ / 128, BS_ / 128), 256, GEMM_SMEM>>>(BS_, HID_, H_ * D_, ctx_p, wo, out);
}

// round 16
// speedup vs baseline: 3.4066x; 1.0669x over previous
#include <cuda_runtime.h>
#include <cuda_bf16.h>
#include <cstdint>

// ---------------- problem constants ----------------
#define B_    2
#define S_    1024
#define HID_  2048
#define H_    32
#define HK_   4
#define D_    128
#define G_    (H_ / HK_)              // 8
#define NQKV_ ((H_ + 2 * HK_) * D_)   // 5120
#define BS_   (B_ * S_)               // 2048
#define EPS_  1e-6f
#define SCALE_ 0.08838834764831845f   // 1/sqrt(128)

// ---------------- scratch (static device memory; no allocs allowed) ----------------
__device__ float g_qkv  [(size_t)BS_ * NQKV_];        // [2048, 5120]
__device__ float g_q    [(size_t)BS_ * H_  * D_];     // [2048, 32, 128]
__device__ float g_k    [(size_t)BS_ * HK_ * D_];     // [2048, 4, 128]
__device__ float g_ctx  [(size_t)BS_ * H_  * D_];     // [2048, 4096]

extern __shared__ char dyn_smem[];

// ---------------- helpers ----------------
__device__ __forceinline__ uint32_t smem_u32(const void* p) {
    uint32_t a;
    asm("{ .reg .u64 t; cvta.to.shared.u64 t, %1; cvt.u32.u64 %0, t; }" : "=r"(a) : "l"(p));
    return a;
}
__device__ __forceinline__ uint32_t f2tf(float x) {   // round-to-nearest tf32
    uint32_t r;
    asm("cvt.rna.tf32.f32 %0, %1;" : "=r"(r) : "f"(x));
    return r;
}
__device__ __forceinline__ float tf2f(float x) { return __uint_as_float(f2tf(x)); }

__device__ __forceinline__ void cp16(uint32_t saddr, const void* gptr) {
    asm volatile("cp.async.cg.shared.global [%0], [%1], 16;" :: "r"(saddr), "l"(gptr) : "memory");
}
#define CP_COMMIT() asm volatile("cp.async.commit_group;" ::: "memory")
#define CP_WAIT1()  asm volatile("cp.async.wait_group 1;" ::: "memory")

// mma.sync m16n8k8 tf32: D(f32) = A(tf32,row) * B(tf32,col) + D
#define MMA_TF32(c, a, b)                                                      \
    asm volatile(                                                              \
        "mma.sync.aligned.m16n8k8.row.col.f32.tf32.tf32.f32 "                  \
        "{%0,%1,%2,%3}, {%4,%5,%6,%7}, {%8,%9}, {%0,%1,%2,%3};"                \
        : "+f"((c)[0]), "+f"((c)[1]), "+f"((c)[2]), "+f"((c)[3])               \
        : "r"((a)[0]), "r"((a)[1]), "r"((a)[2]), "r"((a)[3]),                  \
          "r"((b)[0]), "r"((b)[1]))

// Fragment layouts (lane = threadIdx.x & 31):
//  A m16k8: a0=(r,c) a1=(r+8,c) a2=(r,c+4) a3=(r+8,c+4), r=lane>>2, c=lane&3
//  B k8n8 : b0=(k,n) b1=(k+4,n),                         k=lane&3, n=lane>>2
//  C m16n8: c0=(r,2t) c1=(r,2t+1) c2=(r+8,2t) c3=(r+8,2t+1), t=lane&3

// ============================================================================
// tf32 tensor-core GEMM: C[M,N] = A[M,K] @ B[K,N]   (both row-major, as given)
// 128x128 CTA tile, BK=32, 256 threads (8 warps in 2Mx4N).
// 3-stage cp.async pipeline. __launch_bounds__(256,2): regs capped at 128 so
// TWO CTAs co-reside per SM (smem 2x105KB=210KB <= 228KB) -> cross-CTA overlap
// hides wait_group/bar.sync seams and fragment-LDS latency.
// ============================================================================
#define SROW 36
#define BROW 136
#define ASTG (128 * SROW)              // floats per A stage
#define BSTG (32 * BROW)               // floats per B stage
#define STG  (ASTG + BSTG)
#define NSTAGE 3
#define GEMM_SMEM (NSTAGE * STG * 4)   // 107,520 B

__global__ __launch_bounds__(256, 2)
void mma_gemm_kernel(int M, int N, int K,
                     const float* __restrict__ A,
                     const float* __restrict__ Bm,
                     float* __restrict__ C)
{
    float* sm = (float*)dyn_smem;
    const uint32_t sbase = smem_u32(sm);

    const int tid  = threadIdx.x;
    const int lane = tid & 31;
    const int wid  = tid >> 5;
    const int wm   = (wid & 1) * 64;    // warp M offset
    const int wn   = (wid >> 1) * 32;   // warp N offset
    const int m0 = blockIdx.y * 128;
    const int n0 = blockIdx.x * 128;

    const int ntc = K >> 5;

    float acc[4][4][4];
    #pragma unroll
    for (int i = 0; i < 4; i++)
        #pragma unroll
        for (int j = 0; j < 4; j++)
            #pragma unroll
            for (int r = 0; r < 4; r++) acc[i][j][r] = 0.f;

    // ---- async stage issue ----
    auto issue_stage = [&](int t, int s) {
        const int k0 = t << 5;
        const uint32_t abase = sbase + (uint32_t)(s * STG) * 4u;
        const uint32_t bbase = abase + (uint32_t)ASTG * 4u;
        #pragma unroll
        for (int i = 0; i < 4; ++i) {
            int lin = i * 256 + tid;           // 0..1023
            int ar  = lin >> 3;                // 0..127
            int ac4 = (lin & 7) * 4;           // 0..28
            cp16(abase + (uint32_t)(ar * SROW + ac4) * 4u,
                 A + (size_t)(m0 + ar) * K + k0 + ac4);
            int kk = lin >> 5;                 // 0..31
            int n4 = (lin & 31) * 4;           // 0..124
            cp16(bbase + (uint32_t)(kk * BROW + n4) * 4u,
                 Bm + (size_t)(k0 + kk) * N + n0 + n4);
        }
        CP_COMMIT();
    };

    issue_stage(0, 0);
    issue_stage(1, 1);

    for (int t = 0; t < ntc; ++t) {
        CP_WAIT1();          // stage t resident (newest pending group may still fly)
        __syncthreads();

        // issue next stage (or empty group to keep wait_group accounting uniform)
        if (t + 2 < ntc) issue_stage(t + 2, (t + 2) % NSTAGE);
        else             CP_COMMIT();

        // ---- compute stage t ----
        const float* Ab = sm + (t % NSTAGE) * STG;
        const float* Bb = Ab + ASTG;
        #pragma unroll
        for (int ks = 0; ks < 4; ++ks) {
            uint32_t afr[4][4];
            #pragma unroll
            for (int mt = 0; mt < 4; ++mt) {
                const float* ap = Ab + (wm + mt * 16 + (lane >> 2)) * SROW + ks * 8 + (lane & 3);
                afr[mt][0] = f2tf(ap[0]);
                afr[mt][1] = f2tf(ap[8 * SROW]);
                afr[mt][2] = f2tf(ap[4]);
                afr[mt][3] = f2tf(ap[8 * SROW + 4]);
            }
            uint32_t bfr[4][2];
            #pragma unroll
            for (int nt = 0; nt < 4; ++nt) {
                const float* bp = Bb + (ks * 8 + (lane & 3)) * BROW + wn + nt * 8 + (lane >> 2);
                bfr[nt][0] = f2tf(bp[0]);
                bfr[nt][1] = f2tf(bp[4 * BROW]);
            }
            #pragma unroll
            for (int mt = 0; mt < 4; ++mt)
                #pragma unroll
                for (int nt = 0; nt < 4; ++nt)
                    MMA_TF32(acc[mt][nt], afr[mt], bfr[nt]);
        }
        __syncthreads();     // all warps done with stage t before it is refilled
    }

    // ---- epilogue ----
    #pragma unroll
    for (int mt = 0; mt < 4; ++mt) {
        #pragma unroll
        for (int nt = 0; nt < 4; ++nt) {
            int r0 = m0 + wm + mt * 16 + (lane >> 2);
            int cc = n0 + wn + nt * 8 + (lane & 3) * 2;
            *(float2*)(C + (size_t)r0 * N + cc)       = make_float2(acc[mt][nt][0], acc[mt][nt][1]);
            *(float2*)(C + (size_t)(r0 + 8) * N + cc) = make_float2(acc[mt][nt][2], acc[mt][nt][3]);
        }
    }
}

// ============================================================================
// Fused per-head RMSNorm + RoPE for q and k heads.
// ============================================================================
__global__ __launch_bounds__(128)
void normrope_kernel(const float* __restrict__ cosb,
                     const float* __restrict__ sinb,
                     const float* __restrict__ qw,
                     const float* __restrict__ kw)
{
    const int t  = blockIdx.x;
    const int hh = blockIdx.y;
    const int d  = threadIdx.x;
    const int s  = t & (S_ - 1);

    const float* src;
    const float* w;
    float* dst;
    if (hh < H_) {
        src = g_qkv + (size_t)t * NQKV_ + hh * D_;
        w   = qw;
        dst = g_q + ((size_t)t * H_ + hh) * D_;
    } else {
        int kh = hh - H_;
        src = g_qkv + (size_t)t * NQKV_ + (H_ + kh) * D_;
        w   = kw;
        dst = g_k + ((size_t)t * HK_ + kh) * D_;
    }

    float x = src[d];
    float v = x * x;
    #pragma unroll
    for (int o = 16; o > 0; o >>= 1)
        v += __shfl_xor_sync(0xffffffffu, v, o);

    __shared__ float red[4];
    __shared__ float xn_s[D_];
    int warp = d >> 5, lane = d & 31;
    if (lane == 0) red[warp] = v;
    __syncthreads();
    float total = red[0] + red[1] + red[2] + red[3];
    float xn = w[d] * x * rsqrtf(total * (1.0f / D_) + EPS_);
    xn_s[d] = xn;
    __syncthreads();
    float other = (d < 64) ? xn_s[d + 64] : xn_s[d - 64];
    float rot   = (d < 64) ? -other : other;
    dst[d] = xn * cosb[s * D_ + d] + rot * sinb[s * D_ + d];
}

// ============================================================================
// Flash attention (causal, GQA) with tf32 mma.sync matmuls + fp32 softmax.
// (unchanged from R15 passing version)
// ============================================================================
#define ABM 64
#define ABN 64
#define PPAD 68

struct AttnSmem {
    float Qs[ABM][128];
    float Ks[ABN][128];
    float Vs[ABN][128];
    float Ps[ABM][PPAD];
    float m_s[ABM];
    float l_s[ABM];
    float al_s[ABM];
};

__global__ __launch_bounds__(256, 1)
void attn_kernel()
{
    AttnSmem& sm = *reinterpret_cast<AttnSmem*>(dyn_smem);
    const int tid  = threadIdx.x;
    const int lane = tid & 31;
    const int wid  = tid >> 5;
    const int qw   = (wid & 3) * 16;    // q-row group
    const int kvw  = (wid >> 2) * 32;   // kv-col group (S phase)
    const int dw   = (wid >> 2) * 64;   // d-col group (PV phase)

    const int qt = blockIdx.x;
    const int h  = blockIdx.y;
    const int b  = blockIdx.z;
    const int kh = h / G_;
    const int t0 = b * S_ + qt * ABM;

    const int lr = lane >> 2;           // 0..7
    const int lc = lane & 3;            // 0..3

    // ---- load Q tile (swizzled, tf32-rounded) ----
    #pragma unroll
    for (int it = 0; it < 8; ++it) {
        int lin = it * 256 + tid;
        int r   = lin >> 5;
        int d4  = (lin & 31) << 2;
        float4 v = *(const float4*)&g_q[((size_t)(t0 + r) * H_ + h) * D_ + d4];
        *(float4*)&sm.Qs[r][d4 ^ ((r & 7) << 2)] =
            make_float4(tf2f(v.x), tf2f(v.y), tf2f(v.z), tf2f(v.w));
    }
    if (tid < ABM) { sm.m_s[tid] = -1e30f; sm.l_s[tid] = 0.f; }

    float o[8][4];
    #pragma unroll
    for (int i = 0; i < 8; i++)
        #pragma unroll
        for (int j = 0; j < 4; j++) o[i][j] = 0.f;

    for (int j = 0; j <= qt; ++j) {
        __syncthreads();

        const int kt0 = b * S_ + j * ABN;
        #pragma unroll
        for (int it = 0; it < 8; ++it) {
            int lin = it * 256 + tid;
            int r   = lin >> 5;
            int d4  = (lin & 31) << 2;
            float4 kv = *(const float4*)&g_k[((size_t)(kt0 + r) * HK_ + kh) * D_ + d4];
            *(float4*)&sm.Ks[r][d4 ^ ((r & 7) << 2)] =
                make_float4(tf2f(kv.x), tf2f(kv.y), tf2f(kv.z), tf2f(kv.w));
            float4 vv = *(const float4*)&g_qkv[(size_t)(kt0 + r) * NQKV_ + (H_ + HK_) * D_ + kh * D_ + d4];
            *(float4*)&sm.Vs[r][d4 ^ ((r & 7) << 3)] =
                make_float4(tf2f(vv.x), tf2f(vv.y), tf2f(vv.z), tf2f(vv.w));
        }
        __syncthreads();

        // ---- S = Q @ K^T ----
        float s[4][4];
        #pragma unroll
        for (int nt = 0; nt < 4; ++nt)
            #pragma unroll
            for (int r = 0; r < 4; ++r) s[nt][r] = 0.f;

        #pragma unroll
        for (int ks = 0; ks < 16; ++ks) {
            uint32_t afr[4];
            {
                int sc = (ks * 8 + lc) ^ (lr << 2);
                const float* r0p = sm.Qs[qw + lr];
                const float* r1p = sm.Qs[qw + lr + 8];
                afr[0] = __float_as_uint(r0p[sc]);
                afr[1] = __float_as_uint(r1p[sc]);
                afr[2] = __float_as_uint(r0p[sc ^ 4]);
                afr[3] = __float_as_uint(r1p[sc ^ 4]);
            }
            #pragma unroll
            for (int nt = 0; nt < 4; ++nt) {
                int sc = (ks * 8 + lc) ^ (lr << 2);
                const float* bp = sm.Ks[kvw + nt * 8 + lr];
                uint32_t bfr[2] = { __float_as_uint(bp[sc]), __float_as_uint(bp[sc ^ 4]) };
                MMA_TF32(s[nt], afr, bfr);
            }
        }

        // ---- scale + causal mask -> Ps ----
        const bool diag = (j == qt);
        const int sr = qw + lr;
        #pragma unroll
        for (int nt = 0; nt < 4; ++nt) {
            int cc = kvw + nt * 8 + lc * 2;
            float v0 = s[nt][0] * SCALE_;
            float v1 = s[nt][1] * SCALE_;
            float v2 = s[nt][2] * SCALE_;
            float v3 = s[nt][3] * SCALE_;
            if (diag) {
                if (cc     > sr)     v0 = -1e30f;
                if (cc + 1 > sr)     v1 = -1e30f;
                if (cc     > sr + 8) v2 = -1e30f;
                if (cc + 1 > sr + 8) v3 = -1e30f;
            }
            sm.Ps[sr][cc]     = v0;
            sm.Ps[sr][cc + 1] = v1;
            sm.Ps[sr + 8][cc]     = v2;
            sm.Ps[sr + 8][cc + 1] = v3;
        }
        __syncthreads();

        // ---- online softmax ----
        {
            int row = tid >> 2, q4 = tid & 3;
            float vals[16];
            float mloc = -1e30f;
            #pragma unroll
            for (int kk = 0; kk < 16; kk++) {
                vals[kk] = sm.Ps[row][q4 * 16 + kk];
                mloc = fmaxf(mloc, vals[kk]);
            }
            mloc = fmaxf(mloc, __shfl_xor_sync(0xffffffffu, mloc, 1));
            mloc = fmaxf(mloc, __shfl_xor_sync(0xffffffffu, mloc, 2));
            float mold = sm.m_s[row];
            float mnew = fmaxf(mold, mloc);
            float ssum = 0.f;
            #pragma unroll
            for (int kk = 0; kk < 16; kk++) {
                float p = __expf(vals[kk] - mnew);
                sm.Ps[row][q4 * 16 + kk] = p;
                ssum += p;
            }
            ssum += __shfl_xor_sync(0xffffffffu, ssum, 1);
            ssum += __shfl_xor_sync(0xffffffffu, ssum, 2);
            if (q4 == 0) {
                float alpha = __expf(mold - mnew);
                sm.al_s[row] = alpha;
                sm.m_s[row]  = mnew;
                sm.l_s[row]  = sm.l_s[row] * alpha + ssum;
            }
        }
        __syncthreads();

        // ---- O = O*alpha + P @ V ----
        {
            float alr0 = sm.al_s[qw + lr];
            float alr1 = sm.al_s[qw + lr + 8];
            #pragma unroll
            for (int nt = 0; nt < 8; ++nt) {
                o[nt][0] *= alr0; o[nt][1] *= alr0;
                o[nt][2] *= alr1; o[nt][3] *= alr1;
            }
            #pragma unroll
            for (int ks = 0; ks < 8; ++ks) {
                uint32_t afr[4];
                const float* ap = &sm.Ps[qw + lr][ks * 8 + lc];
                afr[0] = f2tf(ap[0]);
                afr[1] = f2tf(ap[8 * PPAD]);
                afr[2] = f2tf(ap[4]);
                afr[3] = f2tf(ap[8 * PPAD + 4]);
                #pragma unroll
                for (int nt = 0; nt < 8; ++nt) {
                    int n  = dw + nt * 8 + lr;
                    int sc = n ^ (lc << 3);
                    const float* b0p = sm.Vs[ks * 8 + lc];
                    const float* b1p = sm.Vs[ks * 8 + lc + 4];
                    uint32_t bfr[2] = { __float_as_uint(b0p[sc]),
                                        __float_as_uint(b1p[sc ^ 32]) };
                    MMA_TF32(o[nt], afr, bfr);
                }
            }
        }
    }

    // ---- epilogue ----
    __syncthreads();
    {
        float li0 = 1.f / sm.l_s[qw + lr];
        float li1 = 1.f / sm.l_s[qw + lr + 8];
        int r0 = t0 + qw + lr;
        #pragma unroll
        for (int nt = 0; nt < 8; ++nt) {
            int cc = dw + nt * 8 + lc * 2;
            *(float2*)&g_ctx[((size_t)r0 * H_ + h) * D_ + cc] =
                make_float2(o[nt][0] * li0, o[nt][1] * li0);
            *(float2*)&g_ctx[((size_t)(r0 + 8) * H_ + h) * D_ + cc] =
                make_float2(o[nt][2] * li1, o[nt][3] * li1);
        }
    }
}

// ============================================================================
// launch
// ============================================================================
extern "C" void kernel_launch(void* const* d_in, const int* in_sizes, int n_in,
                              void* d_out, int out_size)
{
    (void)in_sizes; (void)n_in; (void)out_size;
    const float* hs   = (const float*)d_in[0];
    const float* cosb = (const float*)d_in[1];
    const float* sinb = (const float*)d_in[2];
    const float* wqkv = (const float*)d_in[3];
    const float* qw   = (const float*)d_in[4];
    const float* kw   = (const float*)d_in[5];
    const float* wo   = (const float*)d_in[6];
    float* out = (float*)d_out;

    float *qkv_p, *ctx_p;
    cudaGetSymbolAddress((void**)&qkv_p, g_qkv);
    cudaGetSymbolAddress((void**)&ctx_p, g_ctx);

    static int configured = -1;
    if (configured < 0) {
        cudaFuncSetAttribute(mma_gemm_kernel, cudaFuncAttributeMaxDynamicSharedMemorySize, GEMM_SMEM);
        cudaFuncSetAttribute(attn_kernel, cudaFuncAttributeMaxDynamicSharedMemorySize, (int)sizeof(AttnSmem));
        configured = 1;
    }

    // 1) qkv = hidden @ w_qkv   (tf32 mma, cp.async pipeline, 2 CTAs/SM)
    mma_gemm_kernel<<<dim3(NQKV_ / 128, BS_ / 128), 256, GEMM_SMEM>>>(BS_, NQKV_, HID_, hs, wqkv, qkv_p);

    // 2) per-head RMSNorm + RoPE
    normrope_kernel<<<dim3(BS_, H_ + HK_), 128>>>(cosb, sinb, qw, kw);

    // 3) GQA causal flash attention -> g_ctx  (tf32 mma)
    attn_kernel<<<dim3(S_ / ABM, H_, B_), 256, sizeof(AttnSmem)>>>();

    // 4) out = ctx @ w_o        (tf32 mma, cp.async pipeline, 2 CTAs/SM)
    mma_gemm_kernel<<<dim3(HID_ / 128, BS_ / 128), 256, GEMM_SMEM>>>(BS_, HID_, H_ * D_, ctx_p, wo, out);
}